// round 2
// baseline (speedup 1.0000x reference)
#include <cuda_runtime.h>

// Problem constants
#define BB 4
#define CC 256
#define NN 4096
#define DD 32
#define RR 320   // D + D + C rows of fused QKV projection

// Scratch: __device__ globals (no cudaMalloc allowed)
__device__ float g_qkv[(size_t)BB * RR * NN];       // q rows 0-31, k rows 32-63, v rows 64-319
__device__ float g_s[(size_t)BB * NN * NN];         // s^T layout: [b, m, n], softmax over n (contiguous)

// ---------------------------------------------------------------------------
// Kernel 1: fused QKV projection.  Y[b,r,n] = Wcat[r,:] . x[b,:,n] + bias[r]
// Tile 64(r) x 64(n), K=256 in chunks of 16. 256 threads, 4x4 micro-tile.
// ---------------------------------------------------------------------------
__global__ void qkv_kernel(const float* __restrict__ x,
                           const float* __restrict__ Wq, const float* __restrict__ bq,
                           const float* __restrict__ Wk, const float* __restrict__ bk,
                           const float* __restrict__ Wv, const float* __restrict__ bv)
{
    __shared__ float Ws[16][64];
    __shared__ float Xs[16][64];
    const int b  = blockIdx.z;
    const int r0 = blockIdx.y * 64;
    const int n0 = blockIdx.x * 64;
    const int tid = threadIdx.x;
    const int tx = tid & 15, ty = tid >> 4;

    const float* xb = x + (size_t)b * CC * NN;
    float acc[4][4] = {};

    for (int k0 = 0; k0 < CC; k0 += 16) {
        #pragma unroll
        for (int i = 0; i < 4; i++) {
            int idx = tid + i * 256;          // 0..1023
            int rr = idx >> 4, kk = idx & 15;
            int r = r0 + rr, c = k0 + kk;
            float w = (r < 32) ? Wq[r * CC + c]
                    : (r < 64) ? Wk[(r - 32) * CC + c]
                               : Wv[(r - 64) * CC + c];
            Ws[kk][rr] = w;
        }
        #pragma unroll
        for (int i = 0; i < 4; i++) {
            int idx = tid + i * 256;
            int kk = idx >> 6, nn = idx & 63;
            Xs[kk][nn] = xb[(size_t)(k0 + kk) * NN + n0 + nn];
        }
        __syncthreads();
        #pragma unroll
        for (int kk = 0; kk < 16; kk++) {
            float a[4], bx[4];
            #pragma unroll
            for (int i = 0; i < 4; i++) a[i]  = Ws[kk][ty * 4 + i];
            #pragma unroll
            for (int j = 0; j < 4; j++) bx[j] = Xs[kk][tx * 4 + j];
            #pragma unroll
            for (int i = 0; i < 4; i++)
                #pragma unroll
                for (int j = 0; j < 4; j++)
                    acc[i][j] += a[i] * bx[j];
        }
        __syncthreads();
    }

    #pragma unroll
    for (int i = 0; i < 4; i++) {
        int r = r0 + ty * 4 + i;
        float bias = (r < 32) ? bq[r] : (r < 64) ? bk[r - 32] : bv[r - 64];
        float* dst = &g_qkv[((size_t)b * RR + r) * NN + n0 + tx * 4];
        #pragma unroll
        for (int j = 0; j < 4; j++) dst[j] = acc[i][j] + bias;
    }
}

// ---------------------------------------------------------------------------
// Kernel 2: sT[b,m,n] = sum_d k[b,d,m] * q[b,d,n].   K=32 (fits smem fully).
// Tile 64(m) x 64(n), 256 threads, 4x4 micro-tile, float4 smem reads.
// ---------------------------------------------------------------------------
__global__ void scores_kernel()
{
    __shared__ float Ks[32][64];
    __shared__ float Qs[32][64];
    const int b  = blockIdx.z;
    const int m0 = blockIdx.y * 64;
    const int n0 = blockIdx.x * 64;
    const int tid = threadIdx.x;
    const int tx = tid & 15, ty = tid >> 4;

    const float* kp = g_qkv + ((size_t)b * RR + 32) * NN;  // k rows
    const float* qp = g_qkv + (size_t)b * RR * NN;         // q rows

    #pragma unroll
    for (int i = 0; i < 8; i++) {
        int idx = tid + i * 256;            // 0..2047
        int d = idx >> 6, mm = idx & 63;
        Ks[d][mm] = kp[(size_t)d * NN + m0 + mm];
    }
    #pragma unroll
    for (int i = 0; i < 8; i++) {
        int idx = tid + i * 256;
        int d = idx >> 6, nn = idx & 63;
        Qs[d][nn] = qp[(size_t)d * NN + n0 + nn];
    }
    __syncthreads();

    float acc[4][4] = {};
    #pragma unroll
    for (int d = 0; d < 32; d++) {
        float4 a4 = *(const float4*)&Ks[d][ty * 4];
        float4 b4 = *(const float4*)&Qs[d][tx * 4];
        float a[4] = {a4.x, a4.y, a4.z, a4.w};
        float c[4] = {b4.x, b4.y, b4.z, b4.w};
        #pragma unroll
        for (int i = 0; i < 4; i++)
            #pragma unroll
            for (int j = 0; j < 4; j++)
                acc[i][j] += a[i] * c[j];
    }

    #pragma unroll
    for (int i = 0; i < 4; i++) {
        size_t off = ((size_t)b * NN + m0 + ty * 4 + i) * NN + n0 + tx * 4;
        float4 o = make_float4(acc[i][0], acc[i][1], acc[i][2], acc[i][3]);
        *(float4*)&g_s[off] = o;
    }
}

// ---------------------------------------------------------------------------
// Kernel 3: in-place row softmax over the contiguous n axis of sT[b,m,:].
// One block (256 threads) per row; 16 elements/thread held in registers.
// ---------------------------------------------------------------------------
__global__ void softmax_kernel()
{
    __shared__ float red[8];
    float* p = g_s + (size_t)blockIdx.x * NN;
    const int tid = threadIdx.x;

    float v[16];
    float mx = -1e30f;
    #pragma unroll
    for (int i = 0; i < 16; i++) {
        v[i] = p[tid + i * 256];
        mx = fmaxf(mx, v[i]);
    }
    #pragma unroll
    for (int o = 16; o; o >>= 1) mx = fmaxf(mx, __shfl_xor_sync(0xffffffffu, mx, o));
    if ((tid & 31) == 0) red[tid >> 5] = mx;
    __syncthreads();
    mx = red[0];
    #pragma unroll
    for (int i = 1; i < 8; i++) mx = fmaxf(mx, red[i]);

    float sum = 0.f;
    #pragma unroll
    for (int i = 0; i < 16; i++) {
        v[i] = __expf(v[i] - mx);
        sum += v[i];
    }
    #pragma unroll
    for (int o = 16; o; o >>= 1) sum += __shfl_xor_sync(0xffffffffu, sum, o);
    __syncthreads();                 // red reuse
    if ((tid & 31) == 0) red[tid >> 5] = sum;
    __syncthreads();
    sum = 0.f;
    #pragma unroll
    for (int i = 0; i < 8; i++) sum += red[i];

    float inv = 1.0f / sum;
    #pragma unroll
    for (int i = 0; i < 16; i++) p[tid + i * 256] = v[i] * inv;
}

// ---------------------------------------------------------------------------
// Kernel 4 (dominant): o[b,c,m] = sum_n v[b,c,n] * att[b,m,n]; out = x + g*o.
// TN GEMM (both operands K-contiguous). Tile 128(c) x 128(m), K-tile 16.
// 256 threads, 8x8 micro-tile, float4 gmem loads, transposed smem (pad 132).
// ---------------------------------------------------------------------------
__global__ void out_kernel(const float* __restrict__ x,
                           const float* __restrict__ gamma,
                           float* __restrict__ out)
{
    __shared__ float Vs[16][132];
    __shared__ float As[16][132];
    const int b  = blockIdx.z;
    const int c0 = blockIdx.y * 128;
    const int m0 = blockIdx.x * 128;
    const int tid = threadIdx.x;
    const int tx = tid & 15, ty = tid >> 4;

    const float* vp = g_qkv + ((size_t)b * RR + 64) * NN;  // v rows
    const float* ap = g_s + (size_t)b * NN * NN;           // att rows [m, n]

    float acc[8][8] = {};

    for (int k0 = 0; k0 < NN; k0 += 16) {
        #pragma unroll
        for (int i = 0; i < 2; i++) {
            int q = tid + i * 256;            // 0..511 float4 slots
            int row = q >> 2, col4 = q & 3;
            float4 f = *(const float4*)&vp[(size_t)(c0 + row) * NN + k0 + col4 * 4];
            Vs[col4 * 4 + 0][row] = f.x;
            Vs[col4 * 4 + 1][row] = f.y;
            Vs[col4 * 4 + 2][row] = f.z;
            Vs[col4 * 4 + 3][row] = f.w;
        }
        #pragma unroll
        for (int i = 0; i < 2; i++) {
            int q = tid + i * 256;
            int row = q >> 2, col4 = q & 3;
            float4 f = *(const float4*)&ap[(size_t)(m0 + row) * NN + k0 + col4 * 4];
            As[col4 * 4 + 0][row] = f.x;
            As[col4 * 4 + 1][row] = f.y;
            As[col4 * 4 + 2][row] = f.z;
            As[col4 * 4 + 3][row] = f.w;
        }
        __syncthreads();
        #pragma unroll
        for (int kk = 0; kk < 16; kk++) {
            float va[8], aa[8];
            *(float4*)&va[0] = *(const float4*)&Vs[kk][ty * 8];
            *(float4*)&va[4] = *(const float4*)&Vs[kk][ty * 8 + 4];
            *(float4*)&aa[0] = *(const float4*)&As[kk][tx * 8];
            *(float4*)&aa[4] = *(const float4*)&As[kk][tx * 8 + 4];
            #pragma unroll
            for (int i = 0; i < 8; i++)
                #pragma unroll
                for (int j = 0; j < 8; j++)
                    acc[i][j] += va[i] * aa[j];
        }
        __syncthreads();
    }

    const float g = gamma[0];
    #pragma unroll
    for (int i = 0; i < 8; i++) {
        int c = c0 + ty * 8 + i;
        size_t base = ((size_t)b * CC + c) * NN + m0 + tx * 8;
        #pragma unroll
        for (int j = 0; j < 8; j++)
            out[base + j] = x[base + j] + g * acc[i][j];
    }
}

// ---------------------------------------------------------------------------
extern "C" void kernel_launch(void* const* d_in, const int* in_sizes, int n_in,
                              void* d_out, int out_size)
{
    const float* x     = (const float*)d_in[0];
    const float* Wq    = (const float*)d_in[1];
    const float* bq    = (const float*)d_in[2];
    const float* Wk    = (const float*)d_in[3];
    const float* bk    = (const float*)d_in[4];
    const float* Wv    = (const float*)d_in[5];
    const float* bv    = (const float*)d_in[6];
    const float* gamma = (const float*)d_in[7];
    float* out = (float*)d_out;

    qkv_kernel<<<dim3(NN / 64, RR / 64, BB), 256>>>(x, Wq, bq, Wk, bk, Wv, bv);
    scores_kernel<<<dim3(NN / 64, NN / 64, BB), 256>>>();
    softmax_kernel<<<BB * NN, 256>>>();
    out_kernel<<<dim3(NN / 128, CC / 128, BB), 256>>>(x, gamma, out);
}

// round 7
// speedup vs baseline: 1.7189x; 1.7189x over previous
#include <cuda_runtime.h>
#include <cstdint>

// Problem constants
#define BB 4
#define CC 256
#define NN 4096
#define DD 32
#define RR 320   // D + D + C rows of fused QKV projection

// Scratch: __device__ globals (no cudaMalloc allowed)
__device__ float g_qkv[(size_t)BB * RR * NN];       // q rows 0-31, k rows 32-63, v rows 64-319
__device__ float g_s[(size_t)BB * NN * NN];         // s^T layout: [b, m, n], softmax over n (contiguous)

// tf32 round-to-nearest conversion (keeps bits in a float container)
__device__ __forceinline__ float to_tf32(float f) {
    uint32_t u;
    asm("cvt.rna.tf32.f32 %0, %1;" : "=r"(u) : "f"(f));
    return __uint_as_float(u);
}

// m16n8k8 tf32 mma (sm_80+ feature, assembles on plain sm_100 target)
__device__ __forceinline__ void mma_tf32(float c[4], const uint32_t a[4], const uint32_t b[2]) {
    asm volatile(
        "mma.sync.aligned.m16n8k8.row.col.f32.tf32.tf32.f32 "
        "{%0,%1,%2,%3}, {%4,%5,%6,%7}, {%8,%9}, {%0,%1,%2,%3};"
        : "+f"(c[0]), "+f"(c[1]), "+f"(c[2]), "+f"(c[3])
        : "r"(a[0]), "r"(a[1]), "r"(a[2]), "r"(a[3]), "r"(b[0]), "r"(b[1]));
}

// ---------------------------------------------------------------------------
// Kernel 1: fused QKV projection.  Y[b,r,n] = Wcat[r,:] . x[b,:,n] + bias[r]
// ---------------------------------------------------------------------------
__global__ void qkv_kernel(const float* __restrict__ x,
                           const float* __restrict__ Wq, const float* __restrict__ bq,
                           const float* __restrict__ Wk, const float* __restrict__ bk,
                           const float* __restrict__ Wv, const float* __restrict__ bv)
{
    __shared__ float Ws[16][64];
    __shared__ float Xs[16][64];
    const int b  = blockIdx.z;
    const int r0 = blockIdx.y * 64;
    const int n0 = blockIdx.x * 64;
    const int tid = threadIdx.x;
    const int tx = tid & 15, ty = tid >> 4;

    const float* xb = x + (size_t)b * CC * NN;
    float acc[4][4] = {};

    for (int k0 = 0; k0 < CC; k0 += 16) {
        #pragma unroll
        for (int i = 0; i < 4; i++) {
            int idx = tid + i * 256;
            int rr = idx >> 4, kk = idx & 15;
            int r = r0 + rr, c = k0 + kk;
            float w = (r < 32) ? Wq[r * CC + c]
                    : (r < 64) ? Wk[(r - 32) * CC + c]
                               : Wv[(r - 64) * CC + c];
            Ws[kk][rr] = w;
        }
        #pragma unroll
        for (int i = 0; i < 4; i++) {
            int idx = tid + i * 256;
            int kk = idx >> 6, nn = idx & 63;
            Xs[kk][nn] = xb[(size_t)(k0 + kk) * NN + n0 + nn];
        }
        __syncthreads();
        #pragma unroll
        for (int kk = 0; kk < 16; kk++) {
            float a[4], bx[4];
            #pragma unroll
            for (int i = 0; i < 4; i++) a[i]  = Ws[kk][ty * 4 + i];
            #pragma unroll
            for (int j = 0; j < 4; j++) bx[j] = Xs[kk][tx * 4 + j];
            #pragma unroll
            for (int i = 0; i < 4; i++)
                #pragma unroll
                for (int j = 0; j < 4; j++)
                    acc[i][j] += a[i] * bx[j];
        }
        __syncthreads();
    }

    #pragma unroll
    for (int i = 0; i < 4; i++) {
        int r = r0 + ty * 4 + i;
        float bias = (r < 32) ? bq[r] : (r < 64) ? bk[r - 32] : bv[r - 64];
        float* dst = &g_qkv[((size_t)b * RR + r) * NN + n0 + tx * 4];
        #pragma unroll
        for (int j = 0; j < 4; j++) dst[j] = acc[i][j] + bias;
    }
}

// ---------------------------------------------------------------------------
// Kernel 2: sT[b,m,n] = sum_d k[b,d,m] * q[b,d,n].   K=32 (fits smem fully).
// ---------------------------------------------------------------------------
__global__ void scores_kernel()
{
    __shared__ float Ks[32][64];
    __shared__ float Qs[32][64];
    const int b  = blockIdx.z;
    const int m0 = blockIdx.y * 64;
    const int n0 = blockIdx.x * 64;
    const int tid = threadIdx.x;
    const int tx = tid & 15, ty = tid >> 4;

    const float* kp = g_qkv + ((size_t)b * RR + 32) * NN;
    const float* qp = g_qkv + (size_t)b * RR * NN;

    #pragma unroll
    for (int i = 0; i < 8; i++) {
        int idx = tid + i * 256;
        int d = idx >> 6, mm = idx & 63;
        Ks[d][mm] = kp[(size_t)d * NN + m0 + mm];
    }
    #pragma unroll
    for (int i = 0; i < 8; i++) {
        int idx = tid + i * 256;
        int d = idx >> 6, nn = idx & 63;
        Qs[d][nn] = qp[(size_t)d * NN + n0 + nn];
    }
    __syncthreads();

    float acc[4][4] = {};
    #pragma unroll
    for (int d = 0; d < 32; d++) {
        float4 a4 = *(const float4*)&Ks[d][ty * 4];
        float4 b4 = *(const float4*)&Qs[d][tx * 4];
        float a[4] = {a4.x, a4.y, a4.z, a4.w};
        float c[4] = {b4.x, b4.y, b4.z, b4.w};
        #pragma unroll
        for (int i = 0; i < 4; i++)
            #pragma unroll
            for (int j = 0; j < 4; j++)
                acc[i][j] += a[i] * c[j];
    }

    #pragma unroll
    for (int i = 0; i < 4; i++) {
        size_t off = ((size_t)b * NN + m0 + ty * 4 + i) * NN + n0 + tx * 4;
        float4 o = make_float4(acc[i][0], acc[i][1], acc[i][2], acc[i][3]);
        *(float4*)&g_s[off] = o;
    }
}

// ---------------------------------------------------------------------------
// Kernel 3: in-place row softmax over the contiguous n axis of sT[b,m,:].
// ---------------------------------------------------------------------------
__global__ void softmax_kernel()
{
    __shared__ float red[8];
    float* p = g_s + (size_t)blockIdx.x * NN;
    const int tid = threadIdx.x;

    float v[16];
    float mx = -1e30f;
    #pragma unroll
    for (int i = 0; i < 16; i++) {
        v[i] = p[tid + i * 256];
        mx = fmaxf(mx, v[i]);
    }
    #pragma unroll
    for (int o = 16; o; o >>= 1) mx = fmaxf(mx, __shfl_xor_sync(0xffffffffu, mx, o));
    if ((tid & 31) == 0) red[tid >> 5] = mx;
    __syncthreads();
    mx = red[0];
    #pragma unroll
    for (int i = 1; i < 8; i++) mx = fmaxf(mx, red[i]);

    float sum = 0.f;
    #pragma unroll
    for (int i = 0; i < 16; i++) {
        v[i] = __expf(v[i] - mx);
        sum += v[i];
    }
    #pragma unroll
    for (int o = 16; o; o >>= 1) sum += __shfl_xor_sync(0xffffffffu, sum, o);
    __syncthreads();
    if ((tid & 31) == 0) red[tid >> 5] = sum;
    __syncthreads();
    sum = 0.f;
    #pragma unroll
    for (int i = 0; i < 8; i++) sum += red[i];

    float inv = 1.0f / sum;
    #pragma unroll
    for (int i = 0; i < 16; i++) p[tid + i * 256] = v[i] * inv;
}

// ---------------------------------------------------------------------------
// Kernel 4 (dominant): mma.sync tf32 GEMM.
// O[b,c,m] = sum_n V[b,c,n] * A[b,m,n];  out = x + gamma * O.
// CTA tile 128(c) x 128(m), 8 warps (2x4), warp tile 64x32, K-tile 16,
// register-staged double-buffered smem, pad 136 -> conflict-free frag reads.
// launch_bounds without min-blocks: let ptxas choose the register budget.
// ---------------------------------------------------------------------------
#define NT (NN / 16)   // 256 k-tiles

__global__ __launch_bounds__(256)
void out_mma_kernel(const float* __restrict__ x,
                    const float* __restrict__ gamma,
                    float* __restrict__ out)
{
    __shared__ float As[2][16][136];   // V tile, [k][c]
    __shared__ float Bs[2][16][136];   // att tile, [k][m]

    const int b  = blockIdx.z;
    const int c0 = blockIdx.y * 128;
    const int m0 = blockIdx.x * 128;
    const int tid = threadIdx.x;
    const int warp = tid >> 5, lane = tid & 31;
    const int wc = warp >> 2, wm = warp & 3;      // 2 x 4 warp grid
    const int g = lane >> 2, t = lane & 3;        // mma group / thread-in-group

    const float* vp = g_qkv + ((size_t)b * RR + 64) * NN;  // V rows [C, N]
    const float* ap = g_s + (size_t)b * NN * NN;           // att rows [m, n]

    // per-thread staging: 2 float4 per operand per tile
    const int cc0 = (tid + 0)   >> 2, kq0 = (tid + 0)   & 3;
    const int cc1 = (tid + 256) >> 2, kq1 = (tid + 256) & 3;

    float acc[4][4][4] = {};

    // prologue: load k-tile 0 into buffer 0
    {
        float4 fA0 = *(const float4*)(vp + (size_t)(c0 + cc0) * NN + kq0 * 4);
        float4 fA1 = *(const float4*)(vp + (size_t)(c0 + cc1) * NN + kq1 * 4);
        float4 fB0 = *(const float4*)(ap + (size_t)(m0 + cc0) * NN + kq0 * 4);
        float4 fB1 = *(const float4*)(ap + (size_t)(m0 + cc1) * NN + kq1 * 4);
        As[0][kq0 * 4 + 0][cc0] = to_tf32(fA0.x); As[0][kq0 * 4 + 1][cc0] = to_tf32(fA0.y);
        As[0][kq0 * 4 + 2][cc0] = to_tf32(fA0.z); As[0][kq0 * 4 + 3][cc0] = to_tf32(fA0.w);
        As[0][kq1 * 4 + 0][cc1] = to_tf32(fA1.x); As[0][kq1 * 4 + 1][cc1] = to_tf32(fA1.y);
        As[0][kq1 * 4 + 2][cc1] = to_tf32(fA1.z); As[0][kq1 * 4 + 3][cc1] = to_tf32(fA1.w);
        Bs[0][kq0 * 4 + 0][cc0] = to_tf32(fB0.x); Bs[0][kq0 * 4 + 1][cc0] = to_tf32(fB0.y);
        Bs[0][kq0 * 4 + 2][cc0] = to_tf32(fB0.z); Bs[0][kq0 * 4 + 3][cc0] = to_tf32(fB0.w);
        Bs[0][kq1 * 4 + 0][cc1] = to_tf32(fB1.x); Bs[0][kq1 * 4 + 1][cc1] = to_tf32(fB1.y);
        Bs[0][kq1 * 4 + 2][cc1] = to_tf32(fB1.z); Bs[0][kq1 * 4 + 3][cc1] = to_tf32(fB1.w);
    }
    __syncthreads();

    for (int kt = 0; kt < NT; kt++) {
        const int buf = kt & 1;

        // stage next tile from gmem into registers (overlaps with compute)
        float4 fA0, fA1, fB0, fB1;
        const bool more = (kt + 1 < NT);
        if (more) {
            const int k0 = (kt + 1) * 16;
            fA0 = *(const float4*)(vp + (size_t)(c0 + cc0) * NN + k0 + kq0 * 4);
            fA1 = *(const float4*)(vp + (size_t)(c0 + cc1) * NN + k0 + kq1 * 4);
            fB0 = *(const float4*)(ap + (size_t)(m0 + cc0) * NN + k0 + kq0 * 4);
            fB1 = *(const float4*)(ap + (size_t)(m0 + cc1) * NN + k0 + kq1 * 4);
        }

        // compute on buf
        #pragma unroll
        for (int ks = 0; ks < 16; ks += 8) {
            uint32_t af[4][4], bf[4][2];
            #pragma unroll
            for (int mi = 0; mi < 4; mi++) {
                const int rb = wc * 64 + mi * 16;
                af[mi][0] = __float_as_uint(As[buf][ks + t][rb + g]);
                af[mi][1] = __float_as_uint(As[buf][ks + t][rb + g + 8]);
                af[mi][2] = __float_as_uint(As[buf][ks + t + 4][rb + g]);
                af[mi][3] = __float_as_uint(As[buf][ks + t + 4][rb + g + 8]);
            }
            #pragma unroll
            for (int ni = 0; ni < 4; ni++) {
                const int cb = wm * 32 + ni * 8;
                bf[ni][0] = __float_as_uint(Bs[buf][ks + t][cb + g]);
                bf[ni][1] = __float_as_uint(Bs[buf][ks + t + 4][cb + g]);
            }
            #pragma unroll
            for (int mi = 0; mi < 4; mi++)
                #pragma unroll
                for (int ni = 0; ni < 4; ni++)
                    mma_tf32(acc[mi][ni], af[mi], bf[ni]);
        }

        // store staged tile into the other buffer
        if (more) {
            const int nb = buf ^ 1;
            As[nb][kq0 * 4 + 0][cc0] = to_tf32(fA0.x); As[nb][kq0 * 4 + 1][cc0] = to_tf32(fA0.y);
            As[nb][kq0 * 4 + 2][cc0] = to_tf32(fA0.z); As[nb][kq0 * 4 + 3][cc0] = to_tf32(fA0.w);
            As[nb][kq1 * 4 + 0][cc1] = to_tf32(fA1.x); As[nb][kq1 * 4 + 1][cc1] = to_tf32(fA1.y);
            As[nb][kq1 * 4 + 2][cc1] = to_tf32(fA1.z); As[nb][kq1 * 4 + 3][cc1] = to_tf32(fA1.w);
            Bs[nb][kq0 * 4 + 0][cc0] = to_tf32(fB0.x); Bs[nb][kq0 * 4 + 1][cc0] = to_tf32(fB0.y);
            Bs[nb][kq0 * 4 + 2][cc0] = to_tf32(fB0.z); Bs[nb][kq0 * 4 + 3][cc0] = to_tf32(fB0.w);
            Bs[nb][kq1 * 4 + 0][cc1] = to_tf32(fB1.x); Bs[nb][kq1 * 4 + 1][cc1] = to_tf32(fB1.y);
            Bs[nb][kq1 * 4 + 2][cc1] = to_tf32(fB1.z); Bs[nb][kq1 * 4 + 3][cc1] = to_tf32(fB1.w);
        }
        __syncthreads();
    }

    // epilogue: out = x + gamma * acc
    const float gm = gamma[0];
    #pragma unroll
    for (int mi = 0; mi < 4; mi++) {
        #pragma unroll
        for (int ni = 0; ni < 4; ni++) {
            const int row0 = wc * 64 + mi * 16 + g;
            const int col  = wm * 32 + ni * 8 + 2 * t;
            size_t i0 = ((size_t)b * CC + c0 + row0) * NN + m0 + col;
            size_t i1 = i0 + (size_t)8 * NN;
            float2 x0 = *(const float2*)(x + i0);
            float2 x1 = *(const float2*)(x + i1);
            float2 o0 = make_float2(x0.x + gm * acc[mi][ni][0], x0.y + gm * acc[mi][ni][1]);
            float2 o1 = make_float2(x1.x + gm * acc[mi][ni][2], x1.y + gm * acc[mi][ni][3]);
            *(float2*)(out + i0) = o0;
            *(float2*)(out + i1) = o1;
        }
    }
}

// ---------------------------------------------------------------------------
extern "C" void kernel_launch(void* const* d_in, const int* in_sizes, int n_in,
                              void* d_out, int out_size)
{
    const float* x     = (const float*)d_in[0];
    const float* Wq    = (const float*)d_in[1];
    const float* bq    = (const float*)d_in[2];
    const float* Wk    = (const float*)d_in[3];
    const float* bk    = (const float*)d_in[4];
    const float* bv    = (const float*)d_in[6];
    const float* Wv    = (const float*)d_in[5];
    const float* gamma = (const float*)d_in[7];
    float* out = (float*)d_out;

    qkv_kernel<<<dim3(NN / 64, RR / 64, BB), 256>>>(x, Wq, bq, Wk, bk, Wv, bv);
    scores_kernel<<<dim3(NN / 64, NN / 64, BB), 256>>>();
    softmax_kernel<<<BB * NN, 256>>>();
    out_mma_kernel<<<dim3(NN / 128, CC / 128, BB), 256>>>(x, gamma, out);
}

// round 9
// speedup vs baseline: 2.1285x; 1.2383x over previous
#include <cuda_runtime.h>
#include <cstdint>

// Problem constants
#define BB 4
#define CC 256
#define NN 4096
#define DD 32
#define RR 320   // D + D + C rows of fused QKV projection

// Scratch: __device__ globals (no cudaMalloc allowed)
__device__ float g_qkv[(size_t)BB * RR * NN];       // q rows 0-31, k rows 32-63, v rows 64-319
__device__ float g_s[(size_t)BB * NN * NN];         // s^T layout: [b, m, n], softmax over n (contiguous)

// m16n8k8 tf32 mma (sm_80+ feature, assembles on plain sm_100 target).
// Inputs are raw fp32 bit patterns; HW truncates mantissa to tf32.
__device__ __forceinline__ void mma_tf32(float c[4], const uint32_t a[4], const uint32_t b[2]) {
    asm volatile(
        "mma.sync.aligned.m16n8k8.row.col.f32.tf32.tf32.f32 "
        "{%0,%1,%2,%3}, {%4,%5,%6,%7}, {%8,%9}, {%0,%1,%2,%3};"
        : "+f"(c[0]), "+f"(c[1]), "+f"(c[2]), "+f"(c[3])
        : "r"(a[0]), "r"(a[1]), "r"(a[2]), "r"(a[3]), "r"(b[0]), "r"(b[1]));
}

__device__ __forceinline__ uint32_t smem_u32(const void* p) {
    uint32_t a;
    asm("{ .reg .u64 t; cvta.to.shared.u64 t, %1; cvt.u32.u64 %0, t; }" : "=r"(a) : "l"(p));
    return a;
}

#define CP_ASYNC16(saddr, gptr) \
    asm volatile("cp.async.cg.shared.global [%0], [%1], 16;" :: "r"(saddr), "l"(gptr))
#define CP_COMMIT() asm volatile("cp.async.commit_group;")
#define CP_WAIT1()  asm volatile("cp.async.wait_group 1;")
#define CP_WAIT0()  asm volatile("cp.async.wait_group 0;")

// ---------------------------------------------------------------------------
// Kernel 1: fused QKV projection.  Y[b,r,n] = Wcat[r,:] . x[b,:,n] + bias[r]
// ---------------------------------------------------------------------------
__global__ void qkv_kernel(const float* __restrict__ x,
                           const float* __restrict__ Wq, const float* __restrict__ bq,
                           const float* __restrict__ Wk, const float* __restrict__ bk,
                           const float* __restrict__ Wv, const float* __restrict__ bv)
{
    __shared__ float Ws[16][64];
    __shared__ float Xs[16][64];
    const int b  = blockIdx.z;
    const int r0 = blockIdx.y * 64;
    const int n0 = blockIdx.x * 64;
    const int tid = threadIdx.x;
    const int tx = tid & 15, ty = tid >> 4;

    const float* xb = x + (size_t)b * CC * NN;
    float acc[4][4] = {};

    for (int k0 = 0; k0 < CC; k0 += 16) {
        #pragma unroll
        for (int i = 0; i < 4; i++) {
            int idx = tid + i * 256;
            int rr = idx >> 4, kk = idx & 15;
            int r = r0 + rr, c = k0 + kk;
            float w = (r < 32) ? Wq[r * CC + c]
                    : (r < 64) ? Wk[(r - 32) * CC + c]
                               : Wv[(r - 64) * CC + c];
            Ws[kk][rr] = w;
        }
        #pragma unroll
        for (int i = 0; i < 4; i++) {
            int idx = tid + i * 256;
            int kk = idx >> 6, nn = idx & 63;
            Xs[kk][nn] = xb[(size_t)(k0 + kk) * NN + n0 + nn];
        }
        __syncthreads();
        #pragma unroll
        for (int kk = 0; kk < 16; kk++) {
            float a[4], bx[4];
            #pragma unroll
            for (int i = 0; i < 4; i++) a[i]  = Ws[kk][ty * 4 + i];
            #pragma unroll
            for (int j = 0; j < 4; j++) bx[j] = Xs[kk][tx * 4 + j];
            #pragma unroll
            for (int i = 0; i < 4; i++)
                #pragma unroll
                for (int j = 0; j < 4; j++)
                    acc[i][j] += a[i] * bx[j];
        }
        __syncthreads();
    }

    #pragma unroll
    for (int i = 0; i < 4; i++) {
        int r = r0 + ty * 4 + i;
        float bias = (r < 32) ? bq[r] : (r < 64) ? bk[r - 32] : bv[r - 64];
        float* dst = &g_qkv[((size_t)b * RR + r) * NN + n0 + tx * 4];
        #pragma unroll
        for (int j = 0; j < 4; j++) dst[j] = acc[i][j] + bias;
    }
}

// ---------------------------------------------------------------------------
// Kernel 2: scores via tf32 mma.  S[b,m,n] = sum_d k[b,d,m] * q[b,d,n].
// CTA 128(m) x 128(n), 8 warps 2(m) x 4(n), warp tile 64x32, K=32 one shot.
// smem [d][m]/[d][n] pitch 136.
// ---------------------------------------------------------------------------
__global__ __launch_bounds__(256)
void scores_mma_kernel()
{
    __shared__ float Ks[32][136];
    __shared__ float Qs[32][136];
    const int b  = blockIdx.z;
    const int m0 = blockIdx.y * 128;
    const int n0 = blockIdx.x * 128;
    const int tid = threadIdx.x;
    const int warp = tid >> 5, lane = tid & 31;
    const int wm = warp >> 2, wn = warp & 3;      // 2 x 4 warp grid
    const int g = lane >> 2, t = lane & 3;

    const float* kp = g_qkv + ((size_t)b * RR + 32) * NN;  // k rows [d][m]
    const float* qp = g_qkv + (size_t)b * RR * NN;         // q rows [d][n]

    // load K, Q tiles: 32 rows x 128 floats each = 1024 float4 per operand
    #pragma unroll
    for (int i = 0; i < 4; i++) {
        int idx = tid + i * 256;
        int d = idx >> 5, mq = idx & 31;
        *(float4*)&Ks[d][mq * 4] = *(const float4*)(kp + (size_t)d * NN + m0 + mq * 4);
        *(float4*)&Qs[d][mq * 4] = *(const float4*)(qp + (size_t)d * NN + n0 + mq * 4);
    }
    __syncthreads();

    float acc[4][4][4] = {};
    #pragma unroll
    for (int ks = 0; ks < 32; ks += 8) {
        uint32_t af[4][4], bf[4][2];
        #pragma unroll
        for (int mi = 0; mi < 4; mi++) {
            const int rb = wm * 64 + mi * 16;
            af[mi][0] = __float_as_uint(Ks[ks + t][rb + g]);
            af[mi][1] = __float_as_uint(Ks[ks + t][rb + g + 8]);
            af[mi][2] = __float_as_uint(Ks[ks + t + 4][rb + g]);
            af[mi][3] = __float_as_uint(Ks[ks + t + 4][rb + g + 8]);
        }
        #pragma unroll
        for (int ni = 0; ni < 4; ni++) {
            const int cb = wn * 32 + ni * 8;
            bf[ni][0] = __float_as_uint(Qs[ks + t][cb + g]);
            bf[ni][1] = __float_as_uint(Qs[ks + t + 4][cb + g]);
        }
        #pragma unroll
        for (int mi = 0; mi < 4; mi++)
            #pragma unroll
            for (int ni = 0; ni < 4; ni++)
                mma_tf32(acc[mi][ni], af[mi], bf[ni]);
    }

    #pragma unroll
    for (int mi = 0; mi < 4; mi++) {
        #pragma unroll
        for (int ni = 0; ni < 4; ni++) {
            const int row0 = m0 + wm * 64 + mi * 16 + g;
            const int col  = n0 + wn * 32 + ni * 8 + 2 * t;
            size_t i0 = ((size_t)b * NN + row0) * NN + col;
            size_t i1 = i0 + (size_t)8 * NN;
            *(float2*)&g_s[i0] = make_float2(acc[mi][ni][0], acc[mi][ni][1]);
            *(float2*)&g_s[i1] = make_float2(acc[mi][ni][2], acc[mi][ni][3]);
        }
    }
}

// ---------------------------------------------------------------------------
// Kernel 3: in-place row softmax over the contiguous n axis of sT[b,m,:].
// ---------------------------------------------------------------------------
__global__ void softmax_kernel()
{
    __shared__ float red[8];
    float* p = g_s + (size_t)blockIdx.x * NN;
    const int tid = threadIdx.x;

    float v[16];
    float mx = -1e30f;
    #pragma unroll
    for (int i = 0; i < 16; i++) {
        v[i] = p[tid + i * 256];
        mx = fmaxf(mx, v[i]);
    }
    #pragma unroll
    for (int o = 16; o; o >>= 1) mx = fmaxf(mx, __shfl_xor_sync(0xffffffffu, mx, o));
    if ((tid & 31) == 0) red[tid >> 5] = mx;
    __syncthreads();
    mx = red[0];
    #pragma unroll
    for (int i = 1; i < 8; i++) mx = fmaxf(mx, red[i]);

    float sum = 0.f;
    #pragma unroll
    for (int i = 0; i < 16; i++) {
        v[i] = __expf(v[i] - mx);
        sum += v[i];
    }
    #pragma unroll
    for (int o = 16; o; o >>= 1) sum += __shfl_xor_sync(0xffffffffu, sum, o);
    __syncthreads();
    if ((tid & 31) == 0) red[tid >> 5] = sum;
    __syncthreads();
    sum = 0.f;
    #pragma unroll
    for (int i = 0; i < 8; i++) sum += red[i];

    float inv = 1.0f / sum;
    #pragma unroll
    for (int i = 0; i < 16; i++) p[tid + i * 256] = v[i] * inv;
}

// ---------------------------------------------------------------------------
// Kernel 4 (dominant): tf32 mma GEMM, cp.async 3-stage pipeline.
// O[b,c,m] = sum_n V[b,c,n] * A[b,m,n];  out = x + gamma * O.
// CTA 128(c) x 256(m), 8 warps 2(c) x 4(m), warp tile 64x64, K-tile 16.
// smem [row][k] pitch 20 floats (bank-safe).
// ---------------------------------------------------------------------------
#define KT 16
#define NT (NN / KT)            // 256 k-tiles
#define APITCH 20
#define A_FLOATS (128 * APITCH) // 2560
#define B_FLOATS (256 * APITCH) // 5120
#define STG_FLOATS (A_FLOATS + B_FLOATS)   // 7680
#define SMEM_BYTES (3 * STG_FLOATS * 4)    // 92160

__global__ __launch_bounds__(256)
void out_mma_kernel(const float* __restrict__ x,
                    const float* __restrict__ gamma,
                    float* __restrict__ out)
{
    extern __shared__ float sm[];
    const uint32_t smb = smem_u32(sm);

    const int b  = blockIdx.z;
    const int c0 = blockIdx.y * 128;
    const int m0 = blockIdx.x * 256;
    const int tid = threadIdx.x;
    const int warp = tid >> 5, lane = tid & 31;
    const int wc = warp >> 2, wm = warp & 3;      // 2(c) x 4(m)
    const int g = lane >> 2, t = lane & 3;

    const float* vp = g_qkv + ((size_t)b * RR + 64) * NN;  // V rows [C][N]
    const float* ap = g_s + (size_t)b * NN * NN;           // att rows [m][n]

    // staging assignment: A chunks (c,kq): 512; B chunks (m,kq): 1024
    const int ac = (tid + 0) >> 2,  akq = tid & 3;          // A chunk 0
    const int ac1 = (tid + 256) >> 2;                       // A chunk 1 (same kq)

    float acc[4][8][4] = {};

    #define ISSUE(kt_, stg_) do {                                               \
        const int _k0 = (kt_) * KT;                                             \
        const uint32_t _sa = smb + (stg_) * STG_FLOATS * 4;                     \
        const uint32_t _sb = _sa + A_FLOATS * 4;                                \
        CP_ASYNC16(_sa + (ac  * APITCH + akq * 4) * 4,                          \
                   vp + (size_t)(c0 + ac)  * NN + _k0 + akq * 4);               \
        CP_ASYNC16(_sa + (ac1 * APITCH + akq * 4) * 4,                          \
                   vp + (size_t)(c0 + ac1) * NN + _k0 + akq * 4);               \
        _Pragma("unroll")                                                       \
        for (int _i = 0; _i < 4; _i++) {                                        \
            int _idx = tid + _i * 256;                                          \
            int _m = _idx >> 2, _kq = _idx & 3;                                 \
            CP_ASYNC16(_sb + (_m * APITCH + _kq * 4) * 4,                       \
                       ap + (size_t)(m0 + _m) * NN + _k0 + _kq * 4);            \
        }                                                                       \
        CP_COMMIT();                                                            \
    } while (0)

    ISSUE(0, 0);
    ISSUE(1, 1);

    #pragma unroll 1
    for (int kt = 0; kt < NT; kt++) {
        const int stg = kt % 3;
        // Normally 2 groups in flight (kt, kt+1) -> wait_group 1 drains group kt.
        // On the final iteration only group kt is in flight -> need wait_group 0.
        if (kt + 1 < NT) { CP_WAIT1(); } else { CP_WAIT0(); }
        __syncthreads();

        const float* As = sm + stg * STG_FLOATS;            // [128][20]
        const float* Bs = As + A_FLOATS;                    // [256][20]

        #pragma unroll
        for (int ks = 0; ks < KT; ks += 8) {
            uint32_t af[4][4], bf[8][2];
            #pragma unroll
            for (int mi = 0; mi < 4; mi++) {
                const int rb = wc * 64 + mi * 16;
                af[mi][0] = __float_as_uint(As[(rb + g)     * APITCH + ks + t]);
                af[mi][1] = __float_as_uint(As[(rb + g + 8) * APITCH + ks + t]);
                af[mi][2] = __float_as_uint(As[(rb + g)     * APITCH + ks + t + 4]);
                af[mi][3] = __float_as_uint(As[(rb + g + 8) * APITCH + ks + t + 4]);
            }
            #pragma unroll
            for (int ni = 0; ni < 8; ni++) {
                const int cb = wm * 64 + ni * 8;
                bf[ni][0] = __float_as_uint(Bs[(cb + g) * APITCH + ks + t]);
                bf[ni][1] = __float_as_uint(Bs[(cb + g) * APITCH + ks + t + 4]);
            }
            #pragma unroll
            for (int mi = 0; mi < 4; mi++)
                #pragma unroll
                for (int ni = 0; ni < 8; ni++)
                    mma_tf32(acc[mi][ni], af[mi], bf[ni]);
        }
        __syncthreads();
        if (kt + 2 < NT) {
            ISSUE(kt + 2, (kt + 2) % 3);
        }
    }
    #undef ISSUE

    // epilogue: out = x + gamma * acc
    const float gm = gamma[0];
    #pragma unroll
    for (int mi = 0; mi < 4; mi++) {
        #pragma unroll
        for (int ni = 0; ni < 8; ni++) {
            const int row0 = c0 + wc * 64 + mi * 16 + g;
            const int col  = m0 + wm * 64 + ni * 8 + 2 * t;
            size_t i0 = ((size_t)b * CC + row0) * NN + col;
            size_t i1 = i0 + (size_t)8 * NN;
            float2 x0 = *(const float2*)(x + i0);
            float2 x1 = *(const float2*)(x + i1);
            *(float2*)(out + i0) = make_float2(x0.x + gm * acc[mi][ni][0],
                                               x0.y + gm * acc[mi][ni][1]);
            *(float2*)(out + i1) = make_float2(x1.x + gm * acc[mi][ni][2],
                                               x1.y + gm * acc[mi][ni][3]);
        }
    }
}

// ---------------------------------------------------------------------------
extern "C" void kernel_launch(void* const* d_in, const int* in_sizes, int n_in,
                              void* d_out, int out_size)
{
    const float* x     = (const float*)d_in[0];
    const float* Wq    = (const float*)d_in[1];
    const float* bq    = (const float*)d_in[2];
    const float* Wk    = (const float*)d_in[3];
    const float* bk    = (const float*)d_in[4];
    const float* Wv    = (const float*)d_in[5];
    const float* bv    = (const float*)d_in[6];
    const float* gamma = (const float*)d_in[7];
    float* out = (float*)d_out;

    // Unconditional every call: deterministic, no static guards (harness rule).
    cudaFuncSetAttribute(out_mma_kernel,
                         cudaFuncAttributeMaxDynamicSharedMemorySize, SMEM_BYTES);

    qkv_kernel<<<dim3(NN / 64, RR / 64, BB), 256>>>(x, Wq, bq, Wk, bk, Wv, bv);
    scores_mma_kernel<<<dim3(NN / 128, NN / 128, BB), 256>>>();
    softmax_kernel<<<BB * NN, 256>>>();
    out_mma_kernel<<<dim3(NN / 256, CC / 128, BB), 256, SMEM_BYTES>>>(x, gamma, out);
}

// round 10
// speedup vs baseline: 2.5219x; 1.1848x over previous
#include <cuda_runtime.h>
#include <cstdint>

// Problem constants
#define BB 4
#define CC 256
#define NN 4096
#define DD 32
#define RR 320   // D + D + C rows of fused QKV projection

// Scratch: __device__ globals (no cudaMalloc allowed)
__device__ float g_qkv[(size_t)BB * RR * NN];     // q rows 0-31, k rows 32-63, v rows 64-319 (tf32-rna values)
__device__ float g_s[(size_t)BB * NN * NN];       // u = exp(s) unnormalized, [b, m, n] (tf32-rna values)
__device__ float g_partZ[(size_t)BB * NN * 32];   // per-(row, n-chunk) partial sums of u
__device__ float g_Z[(size_t)BB * NN];            // row sums Z[b][m]

// tf32 round-to-nearest (unbiased); result stays in a float container.
__device__ __forceinline__ float tf32r(float f) {
    uint32_t u;
    asm("cvt.rna.tf32.f32 %0, %1;" : "=r"(u) : "f"(f));
    return __uint_as_float(u);
}

// m16n8k8 tf32 mma (sm_80+ feature; assembles on plain sm_100 target).
// Inputs already tf32-valued -> HW RZ truncation is exact.
__device__ __forceinline__ void mma_tf32(float c[4], const uint32_t a[4], const uint32_t b[2]) {
    asm volatile(
        "mma.sync.aligned.m16n8k8.row.col.f32.tf32.tf32.f32 "
        "{%0,%1,%2,%3}, {%4,%5,%6,%7}, {%8,%9}, {%0,%1,%2,%3};"
        : "+f"(c[0]), "+f"(c[1]), "+f"(c[2]), "+f"(c[3])
        : "r"(a[0]), "r"(a[1]), "r"(a[2]), "r"(a[3]), "r"(b[0]), "r"(b[1]));
}

__device__ __forceinline__ uint32_t smem_u32(const void* p) {
    uint32_t a;
    asm("{ .reg .u64 t; cvta.to.shared.u64 t, %1; cvt.u32.u64 %0, t; }" : "=r"(a) : "l"(p));
    return a;
}

#define CP_ASYNC16(saddr, gptr) \
    asm volatile("cp.async.cg.shared.global [%0], [%1], 16;" :: "r"(saddr), "l"(gptr))
#define CP_COMMIT() asm volatile("cp.async.commit_group;")
#define CP_WAIT1()  asm volatile("cp.async.wait_group 1;")
#define CP_WAIT0()  asm volatile("cp.async.wait_group 0;")

// ---------------------------------------------------------------------------
// Kernel 1: fused QKV projection.  Y[b,r,n] = Wcat[r,:] . x[b,:,n] + bias[r]
// Output rounded to tf32 (rna) so downstream mma truncation is exact.
// ---------------------------------------------------------------------------
__global__ void qkv_kernel(const float* __restrict__ x,
                           const float* __restrict__ Wq, const float* __restrict__ bq,
                           const float* __restrict__ Wk, const float* __restrict__ bk,
                           const float* __restrict__ Wv, const float* __restrict__ bv)
{
    __shared__ float Ws[16][64];
    __shared__ float Xs[16][64];
    const int b  = blockIdx.z;
    const int r0 = blockIdx.y * 64;
    const int n0 = blockIdx.x * 64;
    const int tid = threadIdx.x;
    const int tx = tid & 15, ty = tid >> 4;

    const float* xb = x + (size_t)b * CC * NN;
    float acc[4][4] = {};

    for (int k0 = 0; k0 < CC; k0 += 16) {
        #pragma unroll
        for (int i = 0; i < 4; i++) {
            int idx = tid + i * 256;
            int rr = idx >> 4, kk = idx & 15;
            int r = r0 + rr, c = k0 + kk;
            float w = (r < 32) ? Wq[r * CC + c]
                    : (r < 64) ? Wk[(r - 32) * CC + c]
                               : Wv[(r - 64) * CC + c];
            Ws[kk][rr] = w;
        }
        #pragma unroll
        for (int i = 0; i < 4; i++) {
            int idx = tid + i * 256;
            int kk = idx >> 6, nn = idx & 63;
            Xs[kk][nn] = xb[(size_t)(k0 + kk) * NN + n0 + nn];
        }
        __syncthreads();
        #pragma unroll
        for (int kk = 0; kk < 16; kk++) {
            float a[4], bx[4];
            #pragma unroll
            for (int i = 0; i < 4; i++) a[i]  = Ws[kk][ty * 4 + i];
            #pragma unroll
            for (int j = 0; j < 4; j++) bx[j] = Xs[kk][tx * 4 + j];
            #pragma unroll
            for (int i = 0; i < 4; i++)
                #pragma unroll
                for (int j = 0; j < 4; j++)
                    acc[i][j] += a[i] * bx[j];
        }
        __syncthreads();
    }

    #pragma unroll
    for (int i = 0; i < 4; i++) {
        int r = r0 + ty * 4 + i;
        float bias = (r < 32) ? bq[r] : (r < 64) ? bk[r - 32] : bv[r - 64];
        float* dst = &g_qkv[((size_t)b * RR + r) * NN + n0 + tx * 4];
        #pragma unroll
        for (int j = 0; j < 4; j++) dst[j] = tf32r(acc[i][j] + bias);
    }
}

// ---------------------------------------------------------------------------
// Kernel 2: scores + exp + partial row sums (softmax without the extra pass).
// s[b,m,n] = sum_d k[b,d,m] * q[b,d,n];  u = exp(s) (no shift needed:
// |s| <= ~35 << 88, so exp never overflows fp32; Z sums stay finite).
// Writes u (tf32-rna) and per-(row, 128-col chunk) partial sums to g_partZ.
// CTA 128(m) x 128(n), 8 warps 2(m) x 4(n), warp tile 64x32, K=32 one shot.
// ---------------------------------------------------------------------------
__global__ __launch_bounds__(256)
void scores_mma_kernel()
{
    __shared__ float Ks[32][136];
    __shared__ float Qs[32][136];
    __shared__ float rsum[4][128];   // [wn][row]
    const int b  = blockIdx.z;
    const int m0 = blockIdx.y * 128;
    const int n0 = blockIdx.x * 128;
    const int tid = threadIdx.x;
    const int warp = tid >> 5, lane = tid & 31;
    const int wm = warp >> 2, wn = warp & 3;      // 2 x 4 warp grid
    const int g = lane >> 2, t = lane & 3;

    const float* kp = g_qkv + ((size_t)b * RR + 32) * NN;  // k rows [d][m]
    const float* qp = g_qkv + (size_t)b * RR * NN;         // q rows [d][n]

    #pragma unroll
    for (int i = 0; i < 4; i++) {
        int idx = tid + i * 256;
        int d = idx >> 5, mq = idx & 31;
        *(float4*)&Ks[d][mq * 4] = *(const float4*)(kp + (size_t)d * NN + m0 + mq * 4);
        *(float4*)&Qs[d][mq * 4] = *(const float4*)(qp + (size_t)d * NN + n0 + mq * 4);
    }
    __syncthreads();

    float acc[4][4][4] = {};
    #pragma unroll
    for (int ks = 0; ks < 32; ks += 8) {
        uint32_t af[4][4], bf[4][2];
        #pragma unroll
        for (int mi = 0; mi < 4; mi++) {
            const int rb = wm * 64 + mi * 16;
            af[mi][0] = __float_as_uint(Ks[ks + t][rb + g]);
            af[mi][1] = __float_as_uint(Ks[ks + t][rb + g + 8]);
            af[mi][2] = __float_as_uint(Ks[ks + t + 4][rb + g]);
            af[mi][3] = __float_as_uint(Ks[ks + t + 4][rb + g + 8]);
        }
        #pragma unroll
        for (int ni = 0; ni < 4; ni++) {
            const int cb = wn * 32 + ni * 8;
            bf[ni][0] = __float_as_uint(Qs[ks + t][cb + g]);
            bf[ni][1] = __float_as_uint(Qs[ks + t + 4][cb + g]);
        }
        #pragma unroll
        for (int mi = 0; mi < 4; mi++)
            #pragma unroll
            for (int ni = 0; ni < 4; ni++)
                mma_tf32(acc[mi][ni], af[mi], bf[ni]);
    }

    // u = exp(s) (tf32-rna rounded), store, and accumulate per-row partials.
    float part[4][2] = {};   // [mi][row-half]
    #pragma unroll
    for (int mi = 0; mi < 4; mi++) {
        #pragma unroll
        for (int ni = 0; ni < 4; ni++) {
            float u0 = tf32r(__expf(acc[mi][ni][0]));
            float u1 = tf32r(__expf(acc[mi][ni][1]));
            float u2 = tf32r(__expf(acc[mi][ni][2]));
            float u3 = tf32r(__expf(acc[mi][ni][3]));
            const int row0 = m0 + wm * 64 + mi * 16 + g;
            const int col  = n0 + wn * 32 + ni * 8 + 2 * t;
            size_t i0 = ((size_t)b * NN + row0) * NN + col;
            size_t i1 = i0 + (size_t)8 * NN;
            *(float2*)&g_s[i0] = make_float2(u0, u1);
            *(float2*)&g_s[i1] = make_float2(u2, u3);
            part[mi][0] += u0 + u1;
            part[mi][1] += u2 + u3;
        }
    }
    // reduce over t lanes (lane = 4g + t): xor 1, 2 sums within each g-group
    #pragma unroll
    for (int mi = 0; mi < 4; mi++) {
        #pragma unroll
        for (int h = 0; h < 2; h++) {
            float v = part[mi][h];
            v += __shfl_xor_sync(0xffffffffu, v, 1);
            v += __shfl_xor_sync(0xffffffffu, v, 2);
            if (t == 0) rsum[wn][wm * 64 + mi * 16 + h * 8 + g] = v;
        }
    }
    __syncthreads();
    if (tid < 128) {
        float z = rsum[0][tid] + rsum[1][tid] + rsum[2][tid] + rsum[3][tid];
        g_partZ[((size_t)b * NN + m0 + tid) * 32 + (n0 >> 7)] = z;
    }
}

// ---------------------------------------------------------------------------
// Kernel 3: reduce partial Z chunks -> Z[b][m]. 16384 rows, 32 chunks each.
// ---------------------------------------------------------------------------
__global__ void zred_kernel()
{
    int row = blockIdx.x * 128 + threadIdx.x;   // 0 .. BB*NN-1
    const float* p = g_partZ + (size_t)row * 32;
    float s = 0.f;
    #pragma unroll
    for (int i = 0; i < 32; i++) s += p[i];
    g_Z[row] = s;
}

// ---------------------------------------------------------------------------
// Kernel 4 (dominant): tf32 mma GEMM on unnormalized u, cp.async 3-stage.
// O[b,c,m] = (1/Z_m) * sum_n V[b,c,n] * u[b,m,n];  out = x + gamma * O.
// CTA 128(c) x 256(m), 8 warps 2(c) x 4(m), warp tile 64x64, K-tile 16.
// One __syncthreads per k-tile (issue targets a stage all warps finished
// reading before this iteration's barrier).
// ---------------------------------------------------------------------------
#define KT 16
#define NT (NN / KT)            // 256 k-tiles
#define APITCH 20
#define A_FLOATS (128 * APITCH) // 2560
#define B_FLOATS (256 * APITCH) // 5120
#define STG_FLOATS (A_FLOATS + B_FLOATS)   // 7680
#define SMEM_BYTES (3 * STG_FLOATS * 4)    // 92160

__global__ __launch_bounds__(256)
void out_mma_kernel(const float* __restrict__ x,
                    const float* __restrict__ gamma,
                    float* __restrict__ out)
{
    extern __shared__ float sm[];
    const uint32_t smb = smem_u32(sm);

    const int b  = blockIdx.z;
    const int c0 = blockIdx.y * 128;
    const int m0 = blockIdx.x * 256;
    const int tid = threadIdx.x;
    const int warp = tid >> 5, lane = tid & 31;
    const int wc = warp >> 2, wm = warp & 3;      // 2(c) x 4(m)
    const int g = lane >> 2, t = lane & 3;

    const float* vp = g_qkv + ((size_t)b * RR + 64) * NN;  // V rows [C][N]
    const float* ap = g_s + (size_t)b * NN * NN;           // u rows [m][n]

    const int ac = (tid + 0) >> 2,  akq = tid & 3;          // A chunk 0
    const int ac1 = (tid + 256) >> 2;                       // A chunk 1

    float acc[4][8][4] = {};

    #define ISSUE(kt_, stg_) do {                                               \
        const int _k0 = (kt_) * KT;                                             \
        const uint32_t _sa = smb + (stg_) * STG_FLOATS * 4;                     \
        const uint32_t _sb = _sa + A_FLOATS * 4;                                \
        CP_ASYNC16(_sa + (ac  * APITCH + akq * 4) * 4,                          \
                   vp + (size_t)(c0 + ac)  * NN + _k0 + akq * 4);               \
        CP_ASYNC16(_sa + (ac1 * APITCH + akq * 4) * 4,                          \
                   vp + (size_t)(c0 + ac1) * NN + _k0 + akq * 4);               \
        _Pragma("unroll")                                                       \
        for (int _i = 0; _i < 4; _i++) {                                        \
            int _idx = tid + _i * 256;                                          \
            int _m = _idx >> 2, _kq = _idx & 3;                                 \
            CP_ASYNC16(_sb + (_m * APITCH + _kq * 4) * 4,                       \
                       ap + (size_t)(m0 + _m) * NN + _k0 + _kq * 4);            \
        }                                                                       \
        CP_COMMIT();                                                            \
    } while (0)

    ISSUE(0, 0);
    ISSUE(1, 1);

    #pragma unroll 1
    for (int kt = 0; kt < NT; kt++) {
        const int stg = kt % 3;
        // 2 groups normally in flight; final iteration has only its own.
        if (kt + 1 < NT) { CP_WAIT1(); } else { CP_WAIT0(); }
        __syncthreads();

        const float* As = sm + stg * STG_FLOATS;            // [128][20]
        const float* Bs = As + A_FLOATS;                    // [256][20]

        #pragma unroll
        for (int ks = 0; ks < KT; ks += 8) {
            uint32_t af[4][4], bf[8][2];
            #pragma unroll
            for (int mi = 0; mi < 4; mi++) {
                const int rb = wc * 64 + mi * 16;
                af[mi][0] = __float_as_uint(As[(rb + g)     * APITCH + ks + t]);
                af[mi][1] = __float_as_uint(As[(rb + g + 8) * APITCH + ks + t]);
                af[mi][2] = __float_as_uint(As[(rb + g)     * APITCH + ks + t + 4]);
                af[mi][3] = __float_as_uint(As[(rb + g + 8) * APITCH + ks + t + 4]);
            }
            #pragma unroll
            for (int ni = 0; ni < 8; ni++) {
                const int cb = wm * 64 + ni * 8;
                bf[ni][0] = __float_as_uint(Bs[(cb + g) * APITCH + ks + t]);
                bf[ni][1] = __float_as_uint(Bs[(cb + g) * APITCH + ks + t + 4]);
            }
            #pragma unroll
            for (int mi = 0; mi < 4; mi++)
                #pragma unroll
                for (int ni = 0; ni < 8; ni++)
                    mma_tf32(acc[mi][ni], af[mi], bf[ni]);
        }
        // No second barrier: ISSUE below writes stage (kt+2)%3 == (kt-1)%3,
        // which every warp finished reading before this iteration's barrier.
        if (kt + 2 < NT) {
            ISSUE(kt + 2, (kt + 2) % 3);
        }
    }
    #undef ISSUE

    // epilogue: out = x + gamma * acc / Z[col]
    const float gm = gamma[0];
    const float* Zp = g_Z + (size_t)b * NN;
    #pragma unroll
    for (int ni = 0; ni < 8; ni++) {
        const int col = m0 + wm * 64 + ni * 8 + 2 * t;
        const float s0 = gm / Zp[col];
        const float s1 = gm / Zp[col + 1];
        #pragma unroll
        for (int mi = 0; mi < 4; mi++) {
            const int row0 = c0 + wc * 64 + mi * 16 + g;
            size_t i0 = ((size_t)b * CC + row0) * NN + col;
            size_t i1 = i0 + (size_t)8 * NN;
            float2 x0 = *(const float2*)(x + i0);
            float2 x1 = *(const float2*)(x + i1);
            *(float2*)(out + i0) = make_float2(x0.x + s0 * acc[mi][ni][0],
                                               x0.y + s1 * acc[mi][ni][1]);
            *(float2*)(out + i1) = make_float2(x1.x + s0 * acc[mi][ni][2],
                                               x1.y + s1 * acc[mi][ni][3]);
        }
    }
}

// ---------------------------------------------------------------------------
extern "C" void kernel_launch(void* const* d_in, const int* in_sizes, int n_in,
                              void* d_out, int out_size)
{
    const float* x     = (const float*)d_in[0];
    const float* Wq    = (const float*)d_in[1];
    const float* bq    = (const float*)d_in[2];
    const float* Wk    = (const float*)d_in[3];
    const float* bk    = (const float*)d_in[4];
    const float* Wv    = (const float*)d_in[5];
    const float* bv    = (const float*)d_in[6];
    const float* gamma = (const float*)d_in[7];
    float* out = (float*)d_out;

    cudaFuncSetAttribute(out_mma_kernel,
                         cudaFuncAttributeMaxDynamicSharedMemorySize, SMEM_BYTES);

    qkv_kernel<<<dim3(NN / 64, RR / 64, BB), 256>>>(x, Wq, bq, Wk, bk, Wv, bv);
    scores_mma_kernel<<<dim3(NN / 128, NN / 128, BB), 256>>>();
    zred_kernel<<<BB * NN / 128, 128>>>();
    out_mma_kernel<<<dim3(NN / 256, CC / 128, BB), 256, SMEM_BYTES>>>(x, gamma, out);
}

// round 11
// speedup vs baseline: 2.5723x; 1.0200x over previous
#include <cuda_runtime.h>
#include <cstdint>

// Problem constants
#define BB 4
#define CC 256
#define NN 4096
#define DD 32
#define RR 320   // D + D + C rows of fused QKV projection

// Scratch: __device__ globals (no cudaMalloc allowed)
__device__ float g_qkv[(size_t)BB * RR * NN];     // q rows 0-31, k rows 32-63, v rows 64-319 (tf32-rna values)
__device__ float g_s[(size_t)BB * NN * NN];       // u = exp(s) unnormalized, [b, m, n] (tf32-rna values)
__device__ float g_partZ[(size_t)BB * NN * 32];   // per-(row, n-chunk) partial sums of u
__device__ float g_Z[(size_t)BB * NN];            // row sums Z[b][m]

// tf32 round-to-nearest (unbiased); result stays in a float container.
__device__ __forceinline__ float tf32r(float f) {
    uint32_t u;
    asm("cvt.rna.tf32.f32 %0, %1;" : "=r"(u) : "f"(f));
    return __uint_as_float(u);
}

// m16n8k8 tf32 mma (sm_80+ feature; assembles on plain sm_100 target).
// Inputs already tf32-valued -> HW RZ truncation is exact.
__device__ __forceinline__ void mma_tf32(float c[4], const uint32_t a[4], const uint32_t b[2]) {
    asm volatile(
        "mma.sync.aligned.m16n8k8.row.col.f32.tf32.tf32.f32 "
        "{%0,%1,%2,%3}, {%4,%5,%6,%7}, {%8,%9}, {%0,%1,%2,%3};"
        : "+f"(c[0]), "+f"(c[1]), "+f"(c[2]), "+f"(c[3])
        : "r"(a[0]), "r"(a[1]), "r"(a[2]), "r"(a[3]), "r"(b[0]), "r"(b[1]));
}

__device__ __forceinline__ uint32_t smem_u32(const void* p) {
    uint32_t a;
    asm("{ .reg .u64 t; cvta.to.shared.u64 t, %1; cvt.u32.u64 %0, t; }" : "=r"(a) : "l"(p));
    return a;
}

#define CP_ASYNC16(saddr, gptr) \
    asm volatile("cp.async.cg.shared.global [%0], [%1], 16;" :: "r"(saddr), "l"(gptr))
#define CP_COMMIT() asm volatile("cp.async.commit_group;")
#define CP_WAIT1()  asm volatile("cp.async.wait_group 1;")
#define CP_WAIT0()  asm volatile("cp.async.wait_group 0;")

// ---------------------------------------------------------------------------
// Kernel 1: fused QKV projection.  Y[b,r,n] = Wcat[r,:] . x[b,:,n] + bias[r]
// Output rounded to tf32 (rna) so downstream mma truncation is exact.
// ---------------------------------------------------------------------------
__global__ void qkv_kernel(const float* __restrict__ x,
                           const float* __restrict__ Wq, const float* __restrict__ bq,
                           const float* __restrict__ Wk, const float* __restrict__ bk,
                           const float* __restrict__ Wv, const float* __restrict__ bv)
{
    __shared__ float Ws[16][64];
    __shared__ float Xs[16][64];
    const int b  = blockIdx.z;
    const int r0 = blockIdx.y * 64;
    const int n0 = blockIdx.x * 64;
    const int tid = threadIdx.x;
    const int tx = tid & 15, ty = tid >> 4;

    const float* xb = x + (size_t)b * CC * NN;
    float acc[4][4] = {};

    for (int k0 = 0; k0 < CC; k0 += 16) {
        #pragma unroll
        for (int i = 0; i < 4; i++) {
            int idx = tid + i * 256;
            int rr = idx >> 4, kk = idx & 15;
            int r = r0 + rr, c = k0 + kk;
            float w = (r < 32) ? Wq[r * CC + c]
                    : (r < 64) ? Wk[(r - 32) * CC + c]
                               : Wv[(r - 64) * CC + c];
            Ws[kk][rr] = w;
        }
        #pragma unroll
        for (int i = 0; i < 4; i++) {
            int idx = tid + i * 256;
            int kk = idx >> 6, nn = idx & 63;
            Xs[kk][nn] = xb[(size_t)(k0 + kk) * NN + n0 + nn];
        }
        __syncthreads();
        #pragma unroll
        for (int kk = 0; kk < 16; kk++) {
            float a[4], bx[4];
            #pragma unroll
            for (int i = 0; i < 4; i++) a[i]  = Ws[kk][ty * 4 + i];
            #pragma unroll
            for (int j = 0; j < 4; j++) bx[j] = Xs[kk][tx * 4 + j];
            #pragma unroll
            for (int i = 0; i < 4; i++)
                #pragma unroll
                for (int j = 0; j < 4; j++)
                    acc[i][j] += a[i] * bx[j];
        }
        __syncthreads();
    }

    #pragma unroll
    for (int i = 0; i < 4; i++) {
        int r = r0 + ty * 4 + i;
        float bias = (r < 32) ? bq[r] : (r < 64) ? bk[r - 32] : bv[r - 64];
        float* dst = &g_qkv[((size_t)b * RR + r) * NN + n0 + tx * 4];
        #pragma unroll
        for (int j = 0; j < 4; j++) dst[j] = tf32r(acc[i][j] + bias);
    }
}

// ---------------------------------------------------------------------------
// Kernel 2: scores + exp + partial row sums (softmax without the extra pass).
// s[b,m,n] = sum_d k[b,d,m] * q[b,d,n];  u = exp(s) (no shift: |s| small).
// Writes u (tf32-rna) and per-(row, 128-col chunk) partial sums to g_partZ.
// CTA 128(m) x 128(n), 8 warps 2(m) x 4(n), warp tile 64x32, K=32 one shot.
// ---------------------------------------------------------------------------
__global__ __launch_bounds__(256)
void scores_mma_kernel()
{
    __shared__ float Ks[32][136];
    __shared__ float Qs[32][136];
    __shared__ float rsum[4][128];   // [wn][row]
    const int b  = blockIdx.z;
    const int m0 = blockIdx.y * 128;
    const int n0 = blockIdx.x * 128;
    const int tid = threadIdx.x;
    const int warp = tid >> 5, lane = tid & 31;
    const int wm = warp >> 2, wn = warp & 3;      // 2 x 4 warp grid
    const int g = lane >> 2, t = lane & 3;

    const float* kp = g_qkv + ((size_t)b * RR + 32) * NN;  // k rows [d][m]
    const float* qp = g_qkv + (size_t)b * RR * NN;         // q rows [d][n]

    #pragma unroll
    for (int i = 0; i < 4; i++) {
        int idx = tid + i * 256;
        int d = idx >> 5, mq = idx & 31;
        *(float4*)&Ks[d][mq * 4] = *(const float4*)(kp + (size_t)d * NN + m0 + mq * 4);
        *(float4*)&Qs[d][mq * 4] = *(const float4*)(qp + (size_t)d * NN + n0 + mq * 4);
    }
    __syncthreads();

    float acc[4][4][4] = {};
    #pragma unroll
    for (int ks = 0; ks < 32; ks += 8) {
        uint32_t af[4][4], bf[4][2];
        #pragma unroll
        for (int mi = 0; mi < 4; mi++) {
            const int rb = wm * 64 + mi * 16;
            af[mi][0] = __float_as_uint(Ks[ks + t][rb + g]);
            af[mi][1] = __float_as_uint(Ks[ks + t][rb + g + 8]);
            af[mi][2] = __float_as_uint(Ks[ks + t + 4][rb + g]);
            af[mi][3] = __float_as_uint(Ks[ks + t + 4][rb + g + 8]);
        }
        #pragma unroll
        for (int ni = 0; ni < 4; ni++) {
            const int cb = wn * 32 + ni * 8;
            bf[ni][0] = __float_as_uint(Qs[ks + t][cb + g]);
            bf[ni][1] = __float_as_uint(Qs[ks + t + 4][cb + g]);
        }
        #pragma unroll
        for (int mi = 0; mi < 4; mi++)
            #pragma unroll
            for (int ni = 0; ni < 4; ni++)
                mma_tf32(acc[mi][ni], af[mi], bf[ni]);
    }

    // u = exp(s) (tf32-rna rounded), store, and accumulate per-row partials.
    float part[4][2] = {};   // [mi][row-half]
    #pragma unroll
    for (int mi = 0; mi < 4; mi++) {
        #pragma unroll
        for (int ni = 0; ni < 4; ni++) {
            float u0 = tf32r(__expf(acc[mi][ni][0]));
            float u1 = tf32r(__expf(acc[mi][ni][1]));
            float u2 = tf32r(__expf(acc[mi][ni][2]));
            float u3 = tf32r(__expf(acc[mi][ni][3]));
            const int row0 = m0 + wm * 64 + mi * 16 + g;
            const int col  = n0 + wn * 32 + ni * 8 + 2 * t;
            size_t i0 = ((size_t)b * NN + row0) * NN + col;
            size_t i1 = i0 + (size_t)8 * NN;
            *(float2*)&g_s[i0] = make_float2(u0, u1);
            *(float2*)&g_s[i1] = make_float2(u2, u3);
            part[mi][0] += u0 + u1;
            part[mi][1] += u2 + u3;
        }
    }
    #pragma unroll
    for (int mi = 0; mi < 4; mi++) {
        #pragma unroll
        for (int h = 0; h < 2; h++) {
            float v = part[mi][h];
            v += __shfl_xor_sync(0xffffffffu, v, 1);
            v += __shfl_xor_sync(0xffffffffu, v, 2);
            if (t == 0) rsum[wn][wm * 64 + mi * 16 + h * 8 + g] = v;
        }
    }
    __syncthreads();
    if (tid < 128) {
        float z = rsum[0][tid] + rsum[1][tid] + rsum[2][tid] + rsum[3][tid];
        g_partZ[((size_t)b * NN + m0 + tid) * 32 + (n0 >> 7)] = z;
    }
}

// ---------------------------------------------------------------------------
// Kernel 3: reduce partial Z chunks -> Z[b][m]. 16384 rows, 32 chunks each.
// ---------------------------------------------------------------------------
__global__ void zred_kernel()
{
    int row = blockIdx.x * 128 + threadIdx.x;   // 0 .. BB*NN-1
    const float* p = g_partZ + (size_t)row * 32;
    float s = 0.f;
    #pragma unroll
    for (int i = 0; i < 32; i++) s += p[i];
    g_Z[row] = s;
}

// ---------------------------------------------------------------------------
// Kernel 4 (dominant): tf32 mma GEMM on unnormalized u, cp.async 3-stage.
// O[b,c,m] = (1/Z_m) * sum_n V[b,c,n] * u[b,m,n];  out = x + gamma * O.
// 512 threads: CTA 128(c) x 256(m), 16 warps 4(c) x 4(m), warp tile 32x64.
// 16 warps/SM (4/SMSP) for latency hiding; acc 64 floats/thread fits 128 regs.
// ---------------------------------------------------------------------------
#define KT 16
#define NT (NN / KT)            // 256 k-tiles
#define APITCH 20
#define A_FLOATS (128 * APITCH) // 2560
#define B_FLOATS (256 * APITCH) // 5120
#define STG_FLOATS (A_FLOATS + B_FLOATS)   // 7680
#define SMEM_BYTES (3 * STG_FLOATS * 4)    // 92160

__global__ __launch_bounds__(512)
void out_mma_kernel(const float* __restrict__ x,
                    const float* __restrict__ gamma,
                    float* __restrict__ out)
{
    extern __shared__ float sm[];
    const uint32_t smb = smem_u32(sm);

    const int b  = blockIdx.z;
    const int c0 = blockIdx.y * 128;
    const int m0 = blockIdx.x * 256;
    const int tid = threadIdx.x;
    const int warp = tid >> 5, lane = tid & 31;
    const int wc = warp >> 2, wm = warp & 3;      // 4(c) x 4(m)
    const int g = lane >> 2, t = lane & 3;

    const float* vp = g_qkv + ((size_t)b * RR + 64) * NN;  // V rows [C][N]
    const float* ap = g_s + (size_t)b * NN * NN;           // u rows [m][n]

    // staging: A tile 128x16 = 512 float4 (1/thread); B tile 256x16 = 1024 (2/thread)
    const int ac = tid >> 2, akq = tid & 3;

    float acc[2][8][4] = {};

    #define ISSUE(kt_, stg_) do {                                               \
        const int _k0 = (kt_) * KT;                                             \
        const uint32_t _sa = smb + (stg_) * STG_FLOATS * 4;                     \
        const uint32_t _sb = _sa + A_FLOATS * 4;                                \
        CP_ASYNC16(_sa + (ac * APITCH + akq * 4) * 4,                           \
                   vp + (size_t)(c0 + ac) * NN + _k0 + akq * 4);                \
        _Pragma("unroll")                                                       \
        for (int _i = 0; _i < 2; _i++) {                                        \
            int _idx = tid + _i * 512;                                          \
            int _m = _idx >> 2, _kq = _idx & 3;                                 \
            CP_ASYNC16(_sb + (_m * APITCH + _kq * 4) * 4,                       \
                       ap + (size_t)(m0 + _m) * NN + _k0 + _kq * 4);            \
        }                                                                       \
        CP_COMMIT();                                                            \
    } while (0)

    ISSUE(0, 0);
    ISSUE(1, 1);

    #pragma unroll 1
    for (int kt = 0; kt < NT; kt++) {
        const int stg = kt % 3;
        if (kt + 1 < NT) { CP_WAIT1(); } else { CP_WAIT0(); }
        __syncthreads();

        const float* As = sm + stg * STG_FLOATS;            // [128][20]
        const float* Bs = As + A_FLOATS;                    // [256][20]

        #pragma unroll
        for (int ks = 0; ks < KT; ks += 8) {
            uint32_t af[2][4], bf[8][2];
            #pragma unroll
            for (int mi = 0; mi < 2; mi++) {
                const int rb = wc * 32 + mi * 16;
                af[mi][0] = __float_as_uint(As[(rb + g)     * APITCH + ks + t]);
                af[mi][1] = __float_as_uint(As[(rb + g + 8) * APITCH + ks + t]);
                af[mi][2] = __float_as_uint(As[(rb + g)     * APITCH + ks + t + 4]);
                af[mi][3] = __float_as_uint(As[(rb + g + 8) * APITCH + ks + t + 4]);
            }
            #pragma unroll
            for (int ni = 0; ni < 8; ni++) {
                const int cb = wm * 64 + ni * 8;
                bf[ni][0] = __float_as_uint(Bs[(cb + g) * APITCH + ks + t]);
                bf[ni][1] = __float_as_uint(Bs[(cb + g) * APITCH + ks + t + 4]);
            }
            #pragma unroll
            for (int mi = 0; mi < 2; mi++)
                #pragma unroll
                for (int ni = 0; ni < 8; ni++)
                    mma_tf32(acc[mi][ni], af[mi], bf[ni]);
        }
        // No second barrier: ISSUE below writes stage (kt+2)%3 == (kt-1)%3,
        // which every warp finished reading before this iteration's barrier.
        if (kt + 2 < NT) {
            ISSUE(kt + 2, (kt + 2) % 3);
        }
    }
    #undef ISSUE

    // epilogue: out = x + gamma * acc / Z[col]
    const float gm = gamma[0];
    const float* Zp = g_Z + (size_t)b * NN;
    #pragma unroll
    for (int ni = 0; ni < 8; ni++) {
        const int col = m0 + wm * 64 + ni * 8 + 2 * t;
        const float s0 = gm / Zp[col];
        const float s1 = gm / Zp[col + 1];
        #pragma unroll
        for (int mi = 0; mi < 2; mi++) {
            const int row0 = c0 + wc * 32 + mi * 16 + g;
            size_t i0 = ((size_t)b * CC + row0) * NN + col;
            size_t i1 = i0 + (size_t)8 * NN;
            float2 x0 = *(const float2*)(x + i0);
            float2 x1 = *(const float2*)(x + i1);
            *(float2*)(out + i0) = make_float2(x0.x + s0 * acc[mi][ni][0],
                                               x0.y + s1 * acc[mi][ni][1]);
            *(float2*)(out + i1) = make_float2(x1.x + s0 * acc[mi][ni][2],
                                               x1.y + s1 * acc[mi][ni][3]);
        }
    }
}

// ---------------------------------------------------------------------------
extern "C" void kernel_launch(void* const* d_in, const int* in_sizes, int n_in,
                              void* d_out, int out_size)
{
    const float* x     = (const float*)d_in[0];
    const float* Wq    = (const float*)d_in[1];
    const float* bq    = (const float*)d_in[2];
    const float* Wk    = (const float*)d_in[3];
    const float* bk    = (const float*)d_in[4];
    const float* Wv    = (const float*)d_in[5];
    const float* bv    = (const float*)d_in[6];
    const float* gamma = (const float*)d_in[7];
    float* out = (float*)d_out;

    cudaFuncSetAttribute(out_mma_kernel,
                         cudaFuncAttributeMaxDynamicSharedMemorySize, SMEM_BYTES);

    qkv_kernel<<<dim3(NN / 64, RR / 64, BB), 256>>>(x, Wq, bq, Wk, bk, Wv, bv);
    scores_mma_kernel<<<dim3(NN / 128, NN / 128, BB), 256>>>();
    zred_kernel<<<BB * NN / 128, 128>>>();
    out_mma_kernel<<<dim3(NN / 256, CC / 128, BB), 512, SMEM_BYTES>>>(x, gamma, out);
}

// round 13
// speedup vs baseline: 2.9963x; 1.1648x over previous
#include <cuda_runtime.h>
#include <cstdint>

// Problem constants
#define BB 4
#define CC 256
#define NN 4096
#define DD 32
#define RR 320   // D + D + C rows of fused QKV projection

// Scratch: __device__ global (no cudaMalloc allowed)
__device__ float g_qkv[(size_t)BB * RR * NN];   // q rows 0-31, k rows 32-63, v rows 64-319 (tf32-rna)

// tf32 round-to-nearest (unbiased); result stays in a float container.
__device__ __forceinline__ float tf32r(float f) {
    uint32_t u;
    asm("cvt.rna.tf32.f32 %0, %1;" : "=r"(u) : "f"(f));
    return __uint_as_float(u);
}

// m16n8k8 tf32 mma (sm_80+; assembles on plain sm_100 target).
// Inputs already tf32-valued -> HW RZ truncation is exact.
__device__ __forceinline__ void mma_tf32(float c[4], const uint32_t a[4], const uint32_t b[2]) {
    asm volatile(
        "mma.sync.aligned.m16n8k8.row.col.f32.tf32.tf32.f32 "
        "{%0,%1,%2,%3}, {%4,%5,%6,%7}, {%8,%9}, {%0,%1,%2,%3};"
        : "+f"(c[0]), "+f"(c[1]), "+f"(c[2]), "+f"(c[3])
        : "r"(a[0]), "r"(a[1]), "r"(a[2]), "r"(a[3]), "r"(b[0]), "r"(b[1]));
}

__device__ __forceinline__ uint32_t smem_u32(const void* p) {
    uint32_t a;
    asm("{ .reg .u64 t; cvta.to.shared.u64 t, %1; cvt.u32.u64 %0, t; }" : "=r"(a) : "l"(p));
    return a;
}

#define CP_ASYNC16(saddr, gptr) \
    asm volatile("cp.async.cg.shared.global [%0], [%1], 16;" :: "r"(saddr), "l"(gptr))
#define CP_COMMIT() asm volatile("cp.async.commit_group;")
#define CP_WAIT1()  asm volatile("cp.async.wait_group 1;")
#define CP_WAIT0()  asm volatile("cp.async.wait_group 0;")

// ---------------------------------------------------------------------------
// Kernel 1: fused QKV projection.  Y[b,r,n] = Wcat[r,:] . x[b,:,n] + bias[r]
// Output rounded to tf32 (rna) so downstream mma truncation is exact.
// ---------------------------------------------------------------------------
__global__ void qkv_kernel(const float* __restrict__ x,
                           const float* __restrict__ Wq, const float* __restrict__ bq,
                           const float* __restrict__ Wk, const float* __restrict__ bk,
                           const float* __restrict__ Wv, const float* __restrict__ bv)
{
    __shared__ float Ws[16][64];
    __shared__ float Xs[16][64];
    const int b  = blockIdx.z;
    const int r0 = blockIdx.y * 64;
    const int n0 = blockIdx.x * 64;
    const int tid = threadIdx.x;
    const int tx = tid & 15, ty = tid >> 4;

    const float* xb = x + (size_t)b * CC * NN;
    float acc[4][4] = {};

    for (int k0 = 0; k0 < CC; k0 += 16) {
        #pragma unroll
        for (int i = 0; i < 4; i++) {
            int idx = tid + i * 256;
            int rr = idx >> 4, kk = idx & 15;
            int r = r0 + rr, c = k0 + kk;
            float w = (r < 32) ? Wq[r * CC + c]
                    : (r < 64) ? Wk[(r - 32) * CC + c]
                               : Wv[(r - 64) * CC + c];
            Ws[kk][rr] = w;
        }
        #pragma unroll
        for (int i = 0; i < 4; i++) {
            int idx = tid + i * 256;
            int kk = idx >> 6, nn = idx & 63;
            Xs[kk][nn] = xb[(size_t)(k0 + kk) * NN + n0 + nn];
        }
        __syncthreads();
        #pragma unroll
        for (int kk = 0; kk < 16; kk++) {
            float a[4], bx[4];
            #pragma unroll
            for (int i = 0; i < 4; i++) a[i]  = Ws[kk][ty * 4 + i];
            #pragma unroll
            for (int j = 0; j < 4; j++) bx[j] = Xs[kk][tx * 4 + j];
            #pragma unroll
            for (int i = 0; i < 4; i++)
                #pragma unroll
                for (int j = 0; j < 4; j++)
                    acc[i][j] += a[i] * bx[j];
        }
        __syncthreads();
    }

    #pragma unroll
    for (int i = 0; i < 4; i++) {
        int r = r0 + ty * 4 + i;
        float bias = (r < 32) ? bq[r] : (r < 64) ? bk[r - 32] : bv[r - 64];
        float* dst = &g_qkv[((size_t)b * RR + r) * NN + n0 + tx * 4];
        #pragma unroll
        for (int j = 0; j < 4; j++) dst[j] = tf32r(acc[i][j] + bias);
    }
}

// ---------------------------------------------------------------------------
// Kernel 2 (fused attention): per CTA: m-block 128, full C=256, loop n tiles
// of 64. s = k^T q (mma, K=32) -> u = tf32r(exp(s)) in smem -> O^T += u * V^T
// (mma, K=64). Z accumulated in registers over the full n range.
// out = x + gamma * O / Z.  No u / partZ / Z global traffic at all.
//
// smem layout (floats):
//   Ks  [128][36]  k-block transposed [m][d]      (A-reads: banks 4g+t, clean)
//   uS  [128][68]  u tile [m][n]                  (A-reads: banks 4g+t, clean)
//   Zs  [4][128], Zf [128]
//   Qs  [2][32][72]  q n-tile [d][n]              (B-reads: banks 8t+g, clean)
//   Vs  [2][256][68] V n-tile [c][n]              (B-reads: banks 4g+t, clean)
// ---------------------------------------------------------------------------
#define NTILE 64
#define NIT (NN / NTILE)        // 64 iterations
#define KSP 36
#define USP 68
#define QSP 72
#define VSP 68
#define KS_OFF 0                             // 128*36   = 4608
#define US_OFF 4608                          // 128*68   = 8704
#define ZS_OFF (US_OFF + 8704)               // 4*128    = 512
#define ZF_OFF (ZS_OFF + 512)                // 128
#define QS_OFF (ZF_OFF + 128)                // 2*32*72  = 4608
#define VS_OFF (QS_OFF + 4608)               // 2*256*68 = 34816
#define FUSED_FLOATS (VS_OFF + 34816)        // 53376
#define FUSED_SMEM (FUSED_FLOATS * 4)        // 213504 B

__global__ __launch_bounds__(512)
void attn_fused_kernel(const float* __restrict__ x,
                       const float* __restrict__ gamma,
                       float* __restrict__ out)
{
    extern __shared__ float sm[];
    const uint32_t smb = smem_u32(sm);

    const int b  = blockIdx.z;
    const int m0 = blockIdx.x * 128;
    const int tid = threadIdx.x;
    const int warp = tid >> 5, lane = tid & 31;
    const int wy = warp >> 2;              // 0..3: m-quarter (both phases)
    const int wx = warp & 3;               // 0..3: n-slice (s) / c-slice (O)
    const int g = lane >> 2, t = lane & 3;

    const float* qp = g_qkv + (size_t)b * RR * NN;          // q [d][n]
    const float* kp = qp + (size_t)32 * NN;                 // k [d][m]
    const float* vp = qp + (size_t)64 * NN;                 // V [c][n]

    float* Ks = sm + KS_OFF;
    float* uS = sm + US_OFF;
    float* Zs = sm + ZS_OFF;
    float* Zf = sm + ZF_OFF;

    // Load k-block transposed into Ks[m][d] (once).
    #pragma unroll
    for (int i = 0; i < 2; i++) {
        int idx = tid + i * 512;
        int d = idx >> 5, mm = (idx & 31) * 4;
        float4 f = *(const float4*)(kp + (size_t)d * NN + m0 + mm);
        Ks[(mm + 0) * KSP + d] = f.x;
        Ks[(mm + 1) * KSP + d] = f.y;
        Ks[(mm + 2) * KSP + d] = f.z;
        Ks[(mm + 3) * KSP + d] = f.w;
    }

    // V tile = 256(c) x 64(n) floats = 4096 float4 -> 8 float4 per thread.
    // q tile = 32(d) x 64(n) floats  = 512 float4  -> 1 float4 per thread.
    #define ISSUE(it_, stg_) do {                                              \
        const int _n0 = (it_) * NTILE;                                         \
        const uint32_t _qb = smb + (QS_OFF + (stg_) * 2304) * 4;               \
        const uint32_t _vb = smb + (VS_OFF + (stg_) * 17408) * 4;              \
        { int _d = tid >> 4, _nn = (tid & 15) * 4;                             \
          CP_ASYNC16(_qb + (_d * QSP + _nn) * 4,                               \
                     qp + (size_t)_d * NN + _n0 + _nn); }                      \
        _Pragma("unroll")                                                      \
        for (int _i = 0; _i < 8; _i++) {                                       \
            int _idx = tid + _i * 512;                                         \
            int _c = _idx >> 4, _nn = (_idx & 15) * 4;                         \
            CP_ASYNC16(_vb + (_c * VSP + _nn) * 4,                             \
                       vp + (size_t)_c * NN + _n0 + _nn);                      \
        }                                                                      \
        CP_COMMIT();                                                           \
    } while (0)

    ISSUE(0, 0);
    ISSUE(1, 1);

    float acc[2][8][4] = {};
    float zp[2][2] = {};

    #pragma unroll 1
    for (int it = 0; it < NIT; it++) {
        const int stg = it & 1;
        if (it + 1 < NIT) { CP_WAIT1(); } else { CP_WAIT0(); }
        __syncthreads();   // stage data + (iter 0: Ks) visible; prev O-mma done

        const float* Qst = sm + QS_OFF + stg * 2304;    // [32][72]
        const float* Vst = sm + VS_OFF + stg * 17408;   // [256][68]

        // ---- s-tile: s[m,n] = sum_d k[d,m] q[d,n], warp tile m32 x n16 ----
        float sacc[2][2][4] = {};
        #pragma unroll
        for (int ks = 0; ks < 32; ks += 8) {
            uint32_t af[2][4], bf[2][2];
            #pragma unroll
            for (int mi = 0; mi < 2; mi++) {
                const int rb = wy * 32 + mi * 16;
                af[mi][0] = __float_as_uint(Ks[(rb + g)     * KSP + ks + t]);
                af[mi][1] = __float_as_uint(Ks[(rb + g + 8) * KSP + ks + t]);
                af[mi][2] = __float_as_uint(Ks[(rb + g)     * KSP + ks + t + 4]);
                af[mi][3] = __float_as_uint(Ks[(rb + g + 8) * KSP + ks + t + 4]);
            }
            #pragma unroll
            for (int ni = 0; ni < 2; ni++) {
                const int cb = wx * 16 + ni * 8;
                bf[ni][0] = __float_as_uint(Qst[(ks + t)     * QSP + cb + g]);
                bf[ni][1] = __float_as_uint(Qst[(ks + t + 4) * QSP + cb + g]);
            }
            #pragma unroll
            for (int mi = 0; mi < 2; mi++)
                #pragma unroll
                for (int ni = 0; ni < 2; ni++)
                    mma_tf32(sacc[mi][ni], af[mi], bf[ni]);
        }

        // ---- u = tf32r(exp(s)) -> uS[m][n]; accumulate Z partials ----
        #pragma unroll
        for (int mi = 0; mi < 2; mi++) {
            const int r0 = wy * 32 + mi * 16 + g;
            #pragma unroll
            for (int ni = 0; ni < 2; ni++) {
                const int cc = wx * 16 + ni * 8 + 2 * t;
                float e0 = tf32r(__expf(sacc[mi][ni][0]));
                float e1 = tf32r(__expf(sacc[mi][ni][1]));
                float e2 = tf32r(__expf(sacc[mi][ni][2]));
                float e3 = tf32r(__expf(sacc[mi][ni][3]));
                *(float2*)&uS[(size_t)r0 * USP + cc]       = make_float2(e0, e1);
                *(float2*)&uS[(size_t)(r0 + 8) * USP + cc] = make_float2(e2, e3);
                zp[mi][0] += e0 + e1;
                zp[mi][1] += e2 + e3;
            }
        }
        __syncthreads();   // uS visible to all warps

        // ---- O^T[m,c] += sum_n u[m,n] V[c,n]; warp tile m32 x c64, K=64 ----
        #pragma unroll
        for (int ks = 0; ks < NTILE; ks += 8) {
            uint32_t af2[2][4], bf2[8][2];
            #pragma unroll
            for (int mi = 0; mi < 2; mi++) {
                const int rb = wy * 32 + mi * 16;
                af2[mi][0] = __float_as_uint(uS[(rb + g)     * USP + ks + t]);
                af2[mi][1] = __float_as_uint(uS[(rb + g + 8) * USP + ks + t]);
                af2[mi][2] = __float_as_uint(uS[(rb + g)     * USP + ks + t + 4]);
                af2[mi][3] = __float_as_uint(uS[(rb + g + 8) * USP + ks + t + 4]);
            }
            #pragma unroll
            for (int ni = 0; ni < 8; ni++) {
                const int cb = wx * 64 + ni * 8;
                bf2[ni][0] = __float_as_uint(Vst[(cb + g) * VSP + ks + t]);
                bf2[ni][1] = __float_as_uint(Vst[(cb + g) * VSP + ks + t + 4]);
            }
            #pragma unroll
            for (int mi = 0; mi < 2; mi++)
                #pragma unroll
                for (int ni = 0; ni < 8; ni++)
                    mma_tf32(acc[mi][ni], af2[mi], bf2[ni]);
        }
        __syncthreads();   // all warps done reading Vst/uS before reuse
        if (it + 2 < NIT) {
            ISSUE(it + 2, stg);   // (it+2) & 1 == stg
        }
    }
    #undef ISSUE

    // ---- Z reduction: zp -> Zs[wx][row] -> Zf[row] ----
    #pragma unroll
    for (int mi = 0; mi < 2; mi++) {
        #pragma unroll
        for (int h = 0; h < 2; h++) {
            float v = zp[mi][h];
            v += __shfl_xor_sync(0xffffffffu, v, 1);
            v += __shfl_xor_sync(0xffffffffu, v, 2);
            if (t == 0) Zs[wx * 128 + wy * 32 + mi * 16 + h * 8 + g] = v;
        }
    }
    __syncthreads();
    if (tid < 128)
        Zf[tid] = Zs[tid] + Zs[128 + tid] + Zs[256 + tid] + Zs[384 + tid];
    __syncthreads();

    // ---- epilogue: out = x + gamma * O^T[m,c] / Z[m] ----
    const float gm = gamma[0];
    #pragma unroll
    for (int mi = 0; mi < 2; mi++) {
        const int r0 = wy * 32 + mi * 16 + g;
        const int r1 = r0 + 8;
        const float z0 = gm / Zf[r0];
        const float z1 = gm / Zf[r1];
        #pragma unroll
        for (int ni = 0; ni < 8; ni++) {
            const int c = wx * 64 + ni * 8 + 2 * t;
            size_t i00 = ((size_t)b * CC + c)     * NN + m0 + r0;
            size_t i10 = ((size_t)b * CC + c + 1) * NN + m0 + r0;
            size_t i01 = i00 + 8;   // row r1 = r0+8 along m
            size_t i11 = i10 + 8;
            out[i00] = x[i00] + z0 * acc[mi][ni][0];
            out[i10] = x[i10] + z0 * acc[mi][ni][1];
            out[i01] = x[i01] + z1 * acc[mi][ni][2];
            out[i11] = x[i11] + z1 * acc[mi][ni][3];
        }
    }
}

// ---------------------------------------------------------------------------
extern "C" void kernel_launch(void* const* d_in, const int* in_sizes, int n_in,
                              void* d_out, int out_size)
{
    const float* x     = (const float*)d_in[0];
    const float* Wq    = (const float*)d_in[1];
    const float* bq    = (const float*)d_in[2];
    const float* Wk    = (const float*)d_in[3];
    const float* bk    = (const float*)d_in[4];
    const float* Wv    = (const float*)d_in[5];
    const float* bv    = (const float*)d_in[6];
    const float* gamma = (const float*)d_in[7];
    float* out = (float*)d_out;

    cudaFuncSetAttribute(attn_fused_kernel,
                         cudaFuncAttributeMaxDynamicSharedMemorySize, FUSED_SMEM);

    qkv_kernel<<<dim3(NN / 64, RR / 64, BB), 256>>>(x, Wq, bq, Wk, bk, Wv, bv);
    attn_fused_kernel<<<dim3(NN / 128, 1, BB), 512, FUSED_SMEM>>>(x, gamma, out);
}

// round 14
// speedup vs baseline: 3.7093x; 1.2380x over previous
#include <cuda_runtime.h>
#include <cstdint>

// Problem constants
#define BB 4
#define CC 256
#define NN 4096
#define DD 32
#define RR 320   // D + D + C rows of fused QKV projection

// Scratch: __device__ global (no cudaMalloc allowed)
__device__ float g_qkv[(size_t)BB * RR * NN];   // q rows 0-31, k rows 32-63, v rows 64-319 (tf32-rna)

// tf32 round-to-nearest (unbiased); result stays in a float container.
__device__ __forceinline__ float tf32r(float f) {
    uint32_t u;
    asm("cvt.rna.tf32.f32 %0, %1;" : "=r"(u) : "f"(f));
    return __uint_as_float(u);
}

// m16n8k8 tf32 mma (sm_80+; assembles on plain sm_100 target).
// Inputs already tf32-valued -> HW RZ truncation is exact.
__device__ __forceinline__ void mma_tf32(float c[4], const uint32_t a[4], const uint32_t b[2]) {
    asm volatile(
        "mma.sync.aligned.m16n8k8.row.col.f32.tf32.tf32.f32 "
        "{%0,%1,%2,%3}, {%4,%5,%6,%7}, {%8,%9}, {%0,%1,%2,%3};"
        : "+f"(c[0]), "+f"(c[1]), "+f"(c[2]), "+f"(c[3])
        : "r"(a[0]), "r"(a[1]), "r"(a[2]), "r"(a[3]), "r"(b[0]), "r"(b[1]));
}

__device__ __forceinline__ uint32_t smem_u32(const void* p) {
    uint32_t a;
    asm("{ .reg .u64 t; cvta.to.shared.u64 t, %1; cvt.u32.u64 %0, t; }" : "=r"(a) : "l"(p));
    return a;
}

#define CP_ASYNC16(saddr, gptr) \
    asm volatile("cp.async.cg.shared.global [%0], [%1], 16;" :: "r"(saddr), "l"(gptr))
#define CP_COMMIT() asm volatile("cp.async.commit_group;")
#define CP_WAIT1()  asm volatile("cp.async.wait_group 1;")
#define CP_WAIT0()  asm volatile("cp.async.wait_group 0;")

// ---------------------------------------------------------------------------
// Kernel 1: fused QKV projection via tf32 mma.
// Y[b,r,n] = Wcat[r,:] . x[b,:,n] + bias[r], outputs tf32-rna to g_qkv.
// Inputs staged gmem -> cvt.rna.tf32 -> smem (unbiased), so mma RZ is exact.
// CTA 64(r) x 128(n), full K=256 resident. 8 warps 2(r) x 4(n), warp 32x32.
// smem: Ws[64][260] ([r][c], A-banks 4g+t), Xs[256][136] ([c][n], B-banks 8t+g).
// ---------------------------------------------------------------------------
#define QWP 260
#define QXP 136
#define QKV_FLOATS (64 * QWP + 256 * QXP)     // 16640 + 34816 = 51456
#define QKV_SMEM (QKV_FLOATS * 4)             // 205824 B

__global__ __launch_bounds__(256)
void qkv_mma_kernel(const float* __restrict__ x,
                    const float* __restrict__ Wq, const float* __restrict__ bq,
                    const float* __restrict__ Wk, const float* __restrict__ bk,
                    const float* __restrict__ Wv, const float* __restrict__ bv)
{
    extern __shared__ float sm[];
    float* Ws = sm;              // [64][260]
    float* Xs = sm + 64 * QWP;   // [256][136]

    const int b  = blockIdx.z;
    const int r0 = blockIdx.y * 64;
    const int n0 = blockIdx.x * 128;
    const int tid = threadIdx.x;
    const int warp = tid >> 5, lane = tid & 31;
    const int wr = warp >> 2, wn = warp & 3;     // 2(r) x 4(n)
    const int g = lane >> 2, t = lane & 3;

    const float* xb = x + (size_t)b * CC * NN;

    // Stage W tile: 64 rows x 256 cols = 4096 float4, 16 per thread.
    #pragma unroll
    for (int i = 0; i < 16; i++) {
        int idx = tid + i * 256;
        int row = idx >> 6, c4 = (idx & 63) * 4;
        int r = r0 + row;
        const float* wrow = (r < 32) ? (Wq + (size_t)r * CC)
                          : (r < 64) ? (Wk + (size_t)(r - 32) * CC)
                                     : (Wv + (size_t)(r - 64) * CC);
        float4 f = *(const float4*)(wrow + c4);
        float* d = Ws + row * QWP + c4;
        d[0] = tf32r(f.x); d[1] = tf32r(f.y); d[2] = tf32r(f.z); d[3] = tf32r(f.w);
    }
    // Stage X tile: 256 rows x 128 cols = 8192 float4, 32 per thread.
    #pragma unroll
    for (int i = 0; i < 32; i++) {
        int idx = tid + i * 256;
        int c = idx >> 5, n4 = (idx & 31) * 4;
        float4 f = *(const float4*)(xb + (size_t)c * NN + n0 + n4);
        float* d = Xs + c * QXP + n4;
        d[0] = tf32r(f.x); d[1] = tf32r(f.y); d[2] = tf32r(f.z); d[3] = tf32r(f.w);
    }
    __syncthreads();

    float acc[2][4][4] = {};
    #pragma unroll 4
    for (int ks = 0; ks < 256; ks += 8) {
        uint32_t af[2][4], bf[4][2];
        #pragma unroll
        for (int mi = 0; mi < 2; mi++) {
            const int rb = wr * 32 + mi * 16;
            af[mi][0] = __float_as_uint(Ws[(rb + g)     * QWP + ks + t]);
            af[mi][1] = __float_as_uint(Ws[(rb + g + 8) * QWP + ks + t]);
            af[mi][2] = __float_as_uint(Ws[(rb + g)     * QWP + ks + t + 4]);
            af[mi][3] = __float_as_uint(Ws[(rb + g + 8) * QWP + ks + t + 4]);
        }
        #pragma unroll
        for (int ni = 0; ni < 4; ni++) {
            const int cb = wn * 32 + ni * 8;
            bf[ni][0] = __float_as_uint(Xs[(ks + t)     * QXP + cb + g]);
            bf[ni][1] = __float_as_uint(Xs[(ks + t + 4) * QXP + cb + g]);
        }
        #pragma unroll
        for (int mi = 0; mi < 2; mi++)
            #pragma unroll
            for (int ni = 0; ni < 4; ni++)
                mma_tf32(acc[mi][ni], af[mi], bf[ni]);
    }

    // Epilogue: add bias, rna-round, store (rows r_a = rb+g, r_b = rb+g+8).
    #pragma unroll
    for (int mi = 0; mi < 2; mi++) {
        const int ra = r0 + wr * 32 + mi * 16 + g;
        const int rb2 = ra + 8;
        float ba = (ra  < 32) ? bq[ra] : (ra  < 64) ? bk[ra - 32]  : bv[ra - 64];
        float bb = (rb2 < 32) ? bq[rb2] : (rb2 < 64) ? bk[rb2 - 32] : bv[rb2 - 64];
        #pragma unroll
        for (int ni = 0; ni < 4; ni++) {
            const int col = n0 + wn * 32 + ni * 8 + 2 * t;
            float* d0 = &g_qkv[((size_t)b * RR + ra)  * NN + col];
            float* d1 = &g_qkv[((size_t)b * RR + rb2) * NN + col];
            d0[0] = tf32r(acc[mi][ni][0] + ba);
            d0[1] = tf32r(acc[mi][ni][1] + ba);
            d1[0] = tf32r(acc[mi][ni][2] + bb);
            d1[1] = tf32r(acc[mi][ni][3] + bb);
        }
    }
}

// ---------------------------------------------------------------------------
// Kernel 2 (fused attention): per CTA: m-block 128, full C=256, loop n tiles
// of 64. s = k^T q (mma, K=32) -> u = tf32r(exp(s)) in smem -> O^T += u * V^T
// (mma, K=64). Z accumulated in registers over the full n range.
// out = x + gamma * O / Z.  No u / partZ / Z global traffic at all.
// ---------------------------------------------------------------------------
#define NTILE 64
#define NIT (NN / NTILE)        // 64 iterations
#define KSP 36
#define USP 68
#define QSP 72
#define VSP 68
#define KS_OFF 0                             // 128*36   = 4608
#define US_OFF 4608                          // 128*68   = 8704
#define ZS_OFF (US_OFF + 8704)               // 4*128    = 512
#define ZF_OFF (ZS_OFF + 512)                // 128
#define QS_OFF (ZF_OFF + 128)                // 2*32*72  = 4608
#define VS_OFF (QS_OFF + 4608)               // 2*256*68 = 34816
#define FUSED_FLOATS (VS_OFF + 34816)        // 53376
#define FUSED_SMEM (FUSED_FLOATS * 4)        // 213504 B

__global__ __launch_bounds__(512)
void attn_fused_kernel(const float* __restrict__ x,
                       const float* __restrict__ gamma,
                       float* __restrict__ out)
{
    extern __shared__ float sm[];
    const uint32_t smb = smem_u32(sm);

    const int b  = blockIdx.z;
    const int m0 = blockIdx.x * 128;
    const int tid = threadIdx.x;
    const int warp = tid >> 5, lane = tid & 31;
    const int wy = warp >> 2;              // 0..3: m-quarter (both phases)
    const int wx = warp & 3;               // 0..3: n-slice (s) / c-slice (O)
    const int g = lane >> 2, t = lane & 3;

    const float* qp = g_qkv + (size_t)b * RR * NN;          // q [d][n]
    const float* kp = qp + (size_t)32 * NN;                 // k [d][m]
    const float* vp = qp + (size_t)64 * NN;                 // V [c][n]

    float* Ks = sm + KS_OFF;
    float* uS = sm + US_OFF;
    float* Zs = sm + ZS_OFF;
    float* Zf = sm + ZF_OFF;

    // Load k-block transposed into Ks[m][d] (once).
    #pragma unroll
    for (int i = 0; i < 2; i++) {
        int idx = tid + i * 512;
        int d = idx >> 5, mm = (idx & 31) * 4;
        float4 f = *(const float4*)(kp + (size_t)d * NN + m0 + mm);
        Ks[(mm + 0) * KSP + d] = f.x;
        Ks[(mm + 1) * KSP + d] = f.y;
        Ks[(mm + 2) * KSP + d] = f.z;
        Ks[(mm + 3) * KSP + d] = f.w;
    }

    // V tile = 256(c) x 64(n) floats = 4096 float4 -> 8 float4 per thread.
    // q tile = 32(d) x 64(n) floats  = 512 float4  -> 1 float4 per thread.
    #define ISSUE(it_, stg_) do {                                              \
        const int _n0 = (it_) * NTILE;                                         \
        const uint32_t _qb = smb + (QS_OFF + (stg_) * 2304) * 4;               \
        const uint32_t _vb = smb + (VS_OFF + (stg_) * 17408) * 4;              \
        { int _d = tid >> 4, _nn = (tid & 15) * 4;                             \
          CP_ASYNC16(_qb + (_d * QSP + _nn) * 4,                               \
                     qp + (size_t)_d * NN + _n0 + _nn); }                      \
        _Pragma("unroll")                                                      \
        for (int _i = 0; _i < 8; _i++) {                                       \
            int _idx = tid + _i * 512;                                         \
            int _c = _idx >> 4, _nn = (_idx & 15) * 4;                         \
            CP_ASYNC16(_vb + (_c * VSP + _nn) * 4,                             \
                       vp + (size_t)_c * NN + _n0 + _nn);                      \
        }                                                                      \
        CP_COMMIT();                                                           \
    } while (0)

    ISSUE(0, 0);
    ISSUE(1, 1);

    float acc[2][8][4] = {};
    float zp[2][2] = {};

    #pragma unroll 1
    for (int it = 0; it < NIT; it++) {
        const int stg = it & 1;
        if (it + 1 < NIT) { CP_WAIT1(); } else { CP_WAIT0(); }
        __syncthreads();   // stage data + (iter 0: Ks) visible; prev O-mma done

        const float* Qst = sm + QS_OFF + stg * 2304;    // [32][72]
        const float* Vst = sm + VS_OFF + stg * 17408;   // [256][68]

        // ---- s-tile: s[m,n] = sum_d k[d,m] q[d,n], warp tile m32 x n16 ----
        float sacc[2][2][4] = {};
        #pragma unroll
        for (int ks = 0; ks < 32; ks += 8) {
            uint32_t af[2][4], bf[2][2];
            #pragma unroll
            for (int mi = 0; mi < 2; mi++) {
                const int rb = wy * 32 + mi * 16;
                af[mi][0] = __float_as_uint(Ks[(rb + g)     * KSP + ks + t]);
                af[mi][1] = __float_as_uint(Ks[(rb + g + 8) * KSP + ks + t]);
                af[mi][2] = __float_as_uint(Ks[(rb + g)     * KSP + ks + t + 4]);
                af[mi][3] = __float_as_uint(Ks[(rb + g + 8) * KSP + ks + t + 4]);
            }
            #pragma unroll
            for (int ni = 0; ni < 2; ni++) {
                const int cb = wx * 16 + ni * 8;
                bf[ni][0] = __float_as_uint(Qst[(ks + t)     * QSP + cb + g]);
                bf[ni][1] = __float_as_uint(Qst[(ks + t + 4) * QSP + cb + g]);
            }
            #pragma unroll
            for (int mi = 0; mi < 2; mi++)
                #pragma unroll
                for (int ni = 0; ni < 2; ni++)
                    mma_tf32(sacc[mi][ni], af[mi], bf[ni]);
        }

        // ---- u = tf32r(exp(s)) -> uS[m][n]; accumulate Z partials ----
        #pragma unroll
        for (int mi = 0; mi < 2; mi++) {
            const int r0 = wy * 32 + mi * 16 + g;
            #pragma unroll
            for (int ni = 0; ni < 2; ni++) {
                const int cc = wx * 16 + ni * 8 + 2 * t;
                float e0 = tf32r(__expf(sacc[mi][ni][0]));
                float e1 = tf32r(__expf(sacc[mi][ni][1]));
                float e2 = tf32r(__expf(sacc[mi][ni][2]));
                float e3 = tf32r(__expf(sacc[mi][ni][3]));
                *(float2*)&uS[(size_t)r0 * USP + cc]       = make_float2(e0, e1);
                *(float2*)&uS[(size_t)(r0 + 8) * USP + cc] = make_float2(e2, e3);
                zp[mi][0] += e0 + e1;
                zp[mi][1] += e2 + e3;
            }
        }
        __syncthreads();   // uS visible to all warps

        // ---- O^T[m,c] += sum_n u[m,n] V[c,n]; warp tile m32 x c64, K=64 ----
        #pragma unroll
        for (int ks = 0; ks < NTILE; ks += 8) {
            uint32_t af2[2][4], bf2[8][2];
            #pragma unroll
            for (int mi = 0; mi < 2; mi++) {
                const int rb = wy * 32 + mi * 16;
                af2[mi][0] = __float_as_uint(uS[(rb + g)     * USP + ks + t]);
                af2[mi][1] = __float_as_uint(uS[(rb + g + 8) * USP + ks + t]);
                af2[mi][2] = __float_as_uint(uS[(rb + g)     * USP + ks + t + 4]);
                af2[mi][3] = __float_as_uint(uS[(rb + g + 8) * USP + ks + t + 4]);
            }
            #pragma unroll
            for (int ni = 0; ni < 8; ni++) {
                const int cb = wx * 64 + ni * 8;
                bf2[ni][0] = __float_as_uint(Vst[(cb + g) * VSP + ks + t]);
                bf2[ni][1] = __float_as_uint(Vst[(cb + g) * VSP + ks + t + 4]);
            }
            #pragma unroll
            for (int mi = 0; mi < 2; mi++)
                #pragma unroll
                for (int ni = 0; ni < 8; ni++)
                    mma_tf32(acc[mi][ni], af2[mi], bf2[ni]);
        }
        __syncthreads();   // all warps done reading Vst/uS before reuse
        if (it + 2 < NIT) {
            ISSUE(it + 2, stg);   // (it+2) & 1 == stg
        }
    }
    #undef ISSUE

    // ---- Z reduction: zp -> Zs[wx][row] -> Zf[row] ----
    #pragma unroll
    for (int mi = 0; mi < 2; mi++) {
        #pragma unroll
        for (int h = 0; h < 2; h++) {
            float v = zp[mi][h];
            v += __shfl_xor_sync(0xffffffffu, v, 1);
            v += __shfl_xor_sync(0xffffffffu, v, 2);
            if (t == 0) Zs[wx * 128 + wy * 32 + mi * 16 + h * 8 + g] = v;
        }
    }
    __syncthreads();
    if (tid < 128)
        Zf[tid] = Zs[tid] + Zs[128 + tid] + Zs[256 + tid] + Zs[384 + tid];
    __syncthreads();

    // ---- epilogue: out = x + gamma * O^T[m,c] / Z[m] ----
    const float gm = gamma[0];
    #pragma unroll
    for (int mi = 0; mi < 2; mi++) {
        const int r0 = wy * 32 + mi * 16 + g;
        const int r1 = r0 + 8;
        const float z0 = gm / Zf[r0];
        const float z1 = gm / Zf[r1];
        #pragma unroll
        for (int ni = 0; ni < 8; ni++) {
            const int c = wx * 64 + ni * 8 + 2 * t;
            size_t i00 = ((size_t)b * CC + c)     * NN + m0 + r0;
            size_t i10 = ((size_t)b * CC + c + 1) * NN + m0 + r0;
            size_t i01 = i00 + 8;   // row r1 = r0+8 along m
            size_t i11 = i10 + 8;
            out[i00] = x[i00] + z0 * acc[mi][ni][0];
            out[i10] = x[i10] + z0 * acc[mi][ni][1];
            out[i01] = x[i01] + z1 * acc[mi][ni][2];
            out[i11] = x[i11] + z1 * acc[mi][ni][3];
        }
    }
}

// ---------------------------------------------------------------------------
extern "C" void kernel_launch(void* const* d_in, const int* in_sizes, int n_in,
                              void* d_out, int out_size)
{
    const float* x     = (const float*)d_in[0];
    const float* Wq    = (const float*)d_in[1];
    const float* bq    = (const float*)d_in[2];
    const float* Wk    = (const float*)d_in[3];
    const float* bk    = (const float*)d_in[4];
    const float* Wv    = (const float*)d_in[5];
    const float* bv    = (const float*)d_in[6];
    const float* gamma = (const float*)d_in[7];
    float* out = (float*)d_out;

    cudaFuncSetAttribute(qkv_mma_kernel,
                         cudaFuncAttributeMaxDynamicSharedMemorySize, QKV_SMEM);
    cudaFuncSetAttribute(attn_fused_kernel,
                         cudaFuncAttributeMaxDynamicSharedMemorySize, FUSED_SMEM);

    qkv_mma_kernel<<<dim3(NN / 128, RR / 64, BB), 256, QKV_SMEM>>>(
        x, Wq, bq, Wk, bk, Wv, bv);
    attn_fused_kernel<<<dim3(NN / 128, 1, BB), 512, FUSED_SMEM>>>(x, gamma, out);
}

// round 17
// speedup vs baseline: 3.7114x; 1.0006x over previous
#include <cuda_runtime.h>
#include <cstdint>

// Problem constants
#define BB 4
#define CC 256
#define NN 4096
#define DD 32
#define RR 320   // D + D + C rows of fused QKV projection

// Scratch: __device__ global (no cudaMalloc allowed)
__device__ float g_qkv[(size_t)BB * RR * NN];   // q rows 0-31, k rows 32-63, v rows 64-319 (tf32-rna)

// tf32 round-to-nearest (unbiased); result stays in a float container.
__device__ __forceinline__ float tf32r(float f) {
    uint32_t u;
    asm("cvt.rna.tf32.f32 %0, %1;" : "=r"(u) : "f"(f));
    return __uint_as_float(u);
}

// m16n8k8 tf32 mma (sm_80+; assembles on plain sm_100 target).
// Inputs already tf32-valued -> HW RZ truncation is exact.
__device__ __forceinline__ void mma_tf32(float c[4], const uint32_t a[4], const uint32_t b[2]) {
    asm volatile(
        "mma.sync.aligned.m16n8k8.row.col.f32.tf32.tf32.f32 "
        "{%0,%1,%2,%3}, {%4,%5,%6,%7}, {%8,%9}, {%0,%1,%2,%3};"
        : "+f"(c[0]), "+f"(c[1]), "+f"(c[2]), "+f"(c[3])
        : "r"(a[0]), "r"(a[1]), "r"(a[2]), "r"(a[3]), "r"(b[0]), "r"(b[1]));
}

__device__ __forceinline__ uint32_t smem_u32(const void* p) {
    uint32_t a;
    asm("{ .reg .u64 t; cvta.to.shared.u64 t, %1; cvt.u32.u64 %0, t; }" : "=r"(a) : "l"(p));
    return a;
}

#define CP_ASYNC16(saddr, gptr) \
    asm volatile("cp.async.cg.shared.global [%0], [%1], 16;" :: "r"(saddr), "l"(gptr))
#define CP_COMMIT() asm volatile("cp.async.commit_group;")
#define CP_WAIT1()  asm volatile("cp.async.wait_group 1;")
#define CP_WAIT0()  asm volatile("cp.async.wait_group 0;")

// ---------------------------------------------------------------------------
// Kernel 1: fused QKV projection via tf32 mma.
// Y[b,r,n] = Wcat[r,:] . x[b,:,n] + bias[r], outputs tf32-rna to g_qkv.
// Inputs staged gmem -> cvt.rna.tf32 -> smem (unbiased), so mma RZ is exact.
// CTA 64(r) x 128(n), full K=256 resident. 8 warps 2(r) x 4(n), warp 32x32.
// ---------------------------------------------------------------------------
#define QWP 260
#define QXP 136
#define QKV_FLOATS (64 * QWP + 256 * QXP)     // 51456
#define QKV_SMEM (QKV_FLOATS * 4)             // 205824 B

__global__ __launch_bounds__(256)
void qkv_mma_kernel(const float* __restrict__ x,
                    const float* __restrict__ Wq, const float* __restrict__ bq,
                    const float* __restrict__ Wk, const float* __restrict__ bk,
                    const float* __restrict__ Wv, const float* __restrict__ bv)
{
    extern __shared__ float sm[];
    float* Ws = sm;              // [64][260]
    float* Xs = sm + 64 * QWP;   // [256][136]

    const int b  = blockIdx.z;
    const int r0 = blockIdx.y * 64;
    const int n0 = blockIdx.x * 128;
    const int tid = threadIdx.x;
    const int warp = tid >> 5, lane = tid & 31;
    const int wr = warp >> 2, wn = warp & 3;     // 2(r) x 4(n)
    const int g = lane >> 2, t = lane & 3;

    const float* xb = x + (size_t)b * CC * NN;

    #pragma unroll
    for (int i = 0; i < 16; i++) {
        int idx = tid + i * 256;
        int row = idx >> 6, c4 = (idx & 63) * 4;
        int r = r0 + row;
        const float* wrow = (r < 32) ? (Wq + (size_t)r * CC)
                          : (r < 64) ? (Wk + (size_t)(r - 32) * CC)
                                     : (Wv + (size_t)(r - 64) * CC);
        float4 f = *(const float4*)(wrow + c4);
        float* d = Ws + row * QWP + c4;
        d[0] = tf32r(f.x); d[1] = tf32r(f.y); d[2] = tf32r(f.z); d[3] = tf32r(f.w);
    }
    #pragma unroll
    for (int i = 0; i < 32; i++) {
        int idx = tid + i * 256;
        int c = idx >> 5, n4 = (idx & 31) * 4;
        float4 f = *(const float4*)(xb + (size_t)c * NN + n0 + n4);
        float* d = Xs + c * QXP + n4;
        d[0] = tf32r(f.x); d[1] = tf32r(f.y); d[2] = tf32r(f.z); d[3] = tf32r(f.w);
    }
    __syncthreads();

    float acc[2][4][4] = {};
    #pragma unroll 4
    for (int ks = 0; ks < 256; ks += 8) {
        uint32_t af[2][4], bf[4][2];
        #pragma unroll
        for (int mi = 0; mi < 2; mi++) {
            const int rb = wr * 32 + mi * 16;
            af[mi][0] = __float_as_uint(Ws[(rb + g)     * QWP + ks + t]);
            af[mi][1] = __float_as_uint(Ws[(rb + g + 8) * QWP + ks + t]);
            af[mi][2] = __float_as_uint(Ws[(rb + g)     * QWP + ks + t + 4]);
            af[mi][3] = __float_as_uint(Ws[(rb + g + 8) * QWP + ks + t + 4]);
        }
        #pragma unroll
        for (int ni = 0; ni < 4; ni++) {
            const int cb = wn * 32 + ni * 8;
            bf[ni][0] = __float_as_uint(Xs[(ks + t)     * QXP + cb + g]);
            bf[ni][1] = __float_as_uint(Xs[(ks + t + 4) * QXP + cb + g]);
        }
        #pragma unroll
        for (int mi = 0; mi < 2; mi++)
            #pragma unroll
            for (int ni = 0; ni < 4; ni++)
                mma_tf32(acc[mi][ni], af[mi], bf[ni]);
    }

    #pragma unroll
    for (int mi = 0; mi < 2; mi++) {
        const int ra = r0 + wr * 32 + mi * 16 + g;
        const int rb2 = ra + 8;
        float ba = (ra  < 32) ? bq[ra] : (ra  < 64) ? bk[ra - 32]  : bv[ra - 64];
        float bb = (rb2 < 32) ? bq[rb2] : (rb2 < 64) ? bk[rb2 - 32] : bv[rb2 - 64];
        #pragma unroll
        for (int ni = 0; ni < 4; ni++) {
            const int col = n0 + wn * 32 + ni * 8 + 2 * t;
            float* d0 = &g_qkv[((size_t)b * RR + ra)  * NN + col];
            float* d1 = &g_qkv[((size_t)b * RR + rb2) * NN + col];
            d0[0] = tf32r(acc[mi][ni][0] + ba);
            d0[1] = tf32r(acc[mi][ni][1] + ba);
            d1[0] = tf32r(acc[mi][ni][2] + bb);
            d1[1] = tf32r(acc[mi][ni][3] + bb);
        }
    }
}

// ---------------------------------------------------------------------------
// Kernel 2 (fused attention): per CTA: m-block 128, full C=256, loop n tiles
// of 64. s = k^T q (mma, K=32) -> u = tf32r(exp(s)) in smem -> O^T += u * V^T
// (mma, K=64). Z accumulated in registers over the full n range.
// out = x + gamma * O / Z.  (R14 configuration — known-pass.)
// ---------------------------------------------------------------------------
#define NTILE 64
#define NIT (NN / NTILE)        // 64 iterations
#define KSP 36
#define USP 68
#define QSP 72
#define VSP 68
#define KS_OFF 0                             // 128*36   = 4608
#define US_OFF 4608                          // 128*68   = 8704
#define ZS_OFF (US_OFF + 8704)               // 4*128    = 512
#define ZF_OFF (ZS_OFF + 512)                // 128
#define QS_OFF (ZF_OFF + 128)                // 2*32*72  = 4608
#define VS_OFF (QS_OFF + 4608)               // 2*256*68 = 34816
#define FUSED_FLOATS (VS_OFF + 34816)        // 53376
#define FUSED_SMEM (FUSED_FLOATS * 4)        // 213504 B

__global__ __launch_bounds__(512)
void attn_fused_kernel(const float* __restrict__ x,
                       const float* __restrict__ gamma,
                       float* __restrict__ out)
{
    extern __shared__ float sm[];
    const uint32_t smb = smem_u32(sm);

    const int b  = blockIdx.z;
    const int m0 = blockIdx.x * 128;
    const int tid = threadIdx.x;
    const int warp = tid >> 5, lane = tid & 31;
    const int wy = warp >> 2;              // 0..3: m-quarter (both phases)
    const int wx = warp & 3;               // 0..3: n-slice (s) / c-slice (O)
    const int g = lane >> 2, t = lane & 3;

    const float* qp = g_qkv + (size_t)b * RR * NN;          // q [d][n]
    const float* kp = qp + (size_t)32 * NN;                 // k [d][m]
    const float* vp = qp + (size_t)64 * NN;                 // V [c][n]

    float* Ks = sm + KS_OFF;
    float* uS = sm + US_OFF;
    float* Zs = sm + ZS_OFF;
    float* Zf = sm + ZF_OFF;

    // Load k-block transposed into Ks[m][d] (once).
    #pragma unroll
    for (int i = 0; i < 2; i++) {
        int idx = tid + i * 512;
        int d = idx >> 5, mm = (idx & 31) * 4;
        float4 f = *(const float4*)(kp + (size_t)d * NN + m0 + mm);
        Ks[(mm + 0) * KSP + d] = f.x;
        Ks[(mm + 1) * KSP + d] = f.y;
        Ks[(mm + 2) * KSP + d] = f.z;
        Ks[(mm + 3) * KSP + d] = f.w;
    }

    // V tile = 256(c) x 64(n) floats = 4096 float4 -> 8 float4 per thread.
    // q tile = 32(d) x 64(n) floats  = 512 float4  -> 1 float4 per thread.
    #define ISSUE(it_, stg_) do {                                              \
        const int _n0 = (it_) * NTILE;                                         \
        const uint32_t _qb = smb + (QS_OFF + (stg_) * 2304) * 4;               \
        const uint32_t _vb = smb + (VS_OFF + (stg_) * 17408) * 4;              \
        { int _d = tid >> 4, _nn = (tid & 15) * 4;                             \
          CP_ASYNC16(_qb + (_d * QSP + _nn) * 4,                               \
                     qp + (size_t)_d * NN + _n0 + _nn); }                      \
        _Pragma("unroll")                                                      \
        for (int _i = 0; _i < 8; _i++) {                                       \
            int _idx = tid + _i * 512;                                         \
            int _c = _idx >> 4, _nn = (_idx & 15) * 4;                         \
            CP_ASYNC16(_vb + (_c * VSP + _nn) * 4,                             \
                       vp + (size_t)_c * NN + _n0 + _nn);                      \
        }                                                                      \
        CP_COMMIT();                                                           \
    } while (0)

    ISSUE(0, 0);
    ISSUE(1, 1);

    float acc[2][8][4] = {};
    float zp[2][2] = {};

    #pragma unroll 1
    for (int it = 0; it < NIT; it++) {
        const int stg = it & 1;
        if (it + 1 < NIT) { CP_WAIT1(); } else { CP_WAIT0(); }
        __syncthreads();   // stage data + (iter 0: Ks) visible; prev O-mma done

        const float* Qst = sm + QS_OFF + stg * 2304;    // [32][72]
        const float* Vst = sm + VS_OFF + stg * 17408;   // [256][68]

        // ---- s-tile: s[m,n] = sum_d k[d,m] q[d,n], warp tile m32 x n16 ----
        float sacc[2][2][4] = {};
        #pragma unroll
        for (int ks = 0; ks < 32; ks += 8) {
            uint32_t af[2][4], bf[2][2];
            #pragma unroll
            for (int mi = 0; mi < 2; mi++) {
                const int rb = wy * 32 + mi * 16;
                af[mi][0] = __float_as_uint(Ks[(rb + g)     * KSP + ks + t]);
                af[mi][1] = __float_as_uint(Ks[(rb + g + 8) * KSP + ks + t]);
                af[mi][2] = __float_as_uint(Ks[(rb + g)     * KSP + ks + t + 4]);
                af[mi][3] = __float_as_uint(Ks[(rb + g + 8) * KSP + ks + t + 4]);
            }
            #pragma unroll
            for (int ni = 0; ni < 2; ni++) {
                const int cb = wx * 16 + ni * 8;
                bf[ni][0] = __float_as_uint(Qst[(ks + t)     * QSP + cb + g]);
                bf[ni][1] = __float_as_uint(Qst[(ks + t + 4) * QSP + cb + g]);
            }
            #pragma unroll
            for (int mi = 0; mi < 2; mi++)
                #pragma unroll
                for (int ni = 0; ni < 2; ni++)
                    mma_tf32(sacc[mi][ni], af[mi], bf[ni]);
        }

        // ---- u = tf32r(exp(s)) -> uS[m][n]; accumulate Z partials ----
        #pragma unroll
        for (int mi = 0; mi < 2; mi++) {
            const int r0 = wy * 32 + mi * 16 + g;
            #pragma unroll
            for (int ni = 0; ni < 2; ni++) {
                const int cc = wx * 16 + ni * 8 + 2 * t;
                float e0 = tf32r(__expf(sacc[mi][ni][0]));
                float e1 = tf32r(__expf(sacc[mi][ni][1]));
                float e2 = tf32r(__expf(sacc[mi][ni][2]));
                float e3 = tf32r(__expf(sacc[mi][ni][3]));
                *(float2*)&uS[(size_t)r0 * USP + cc]       = make_float2(e0, e1);
                *(float2*)&uS[(size_t)(r0 + 8) * USP + cc] = make_float2(e2, e3);
                zp[mi][0] += e0 + e1;
                zp[mi][1] += e2 + e3;
            }
        }
        __syncthreads();   // uS visible to all warps

        // ---- O^T[m,c] += sum_n u[m,n] V[c,n]; warp tile m32 x c64, K=64 ----
        #pragma unroll
        for (int ks = 0; ks < NTILE; ks += 8) {
            uint32_t af2[2][4], bf2[8][2];
            #pragma unroll
            for (int mi = 0; mi < 2; mi++) {
                const int rb = wy * 32 + mi * 16;
                af2[mi][0] = __float_as_uint(uS[(rb + g)     * USP + ks + t]);
                af2[mi][1] = __float_as_uint(uS[(rb + g + 8) * USP + ks + t]);
                af2[mi][2] = __float_as_uint(uS[(rb + g)     * USP + ks + t + 4]);
                af2[mi][3] = __float_as_uint(uS[(rb + g + 8) * USP + ks + t + 4]);
            }
            #pragma unroll
            for (int ni = 0; ni < 8; ni++) {
                const int cb = wx * 64 + ni * 8;
                bf2[ni][0] = __float_as_uint(Vst[(cb + g) * VSP + ks + t]);
                bf2[ni][1] = __float_as_uint(Vst[(cb + g) * VSP + ks + t + 4]);
            }
            #pragma unroll
            for (int mi = 0; mi < 2; mi++)
                #pragma unroll
                for (int ni = 0; ni < 8; ni++)
                    mma_tf32(acc[mi][ni], af2[mi], bf2[ni]);
        }
        __syncthreads();   // all warps done reading Vst/uS before reuse
        if (it + 2 < NIT) {
            ISSUE(it + 2, stg);   // (it+2) & 1 == stg
        }
    }
    #undef ISSUE

    // ---- Z reduction: zp -> Zs[wx][row] -> Zf[row] ----
    #pragma unroll
    for (int mi = 0; mi < 2; mi++) {
        #pragma unroll
        for (int h = 0; h < 2; h++) {
            float v = zp[mi][h];
            v += __shfl_xor_sync(0xffffffffu, v, 1);
            v += __shfl_xor_sync(0xffffffffu, v, 2);
            if (t == 0) Zs[wx * 128 + wy * 32 + mi * 16 + h * 8 + g] = v;
        }
    }
    __syncthreads();
    if (tid < 128)
        Zf[tid] = Zs[tid] + Zs[128 + tid] + Zs[256 + tid] + Zs[384 + tid];
    __syncthreads();

    // ---- epilogue: out = x + gamma * O^T[m,c] / Z[m] ----
    const float gm = gamma[0];
    #pragma unroll
    for (int mi = 0; mi < 2; mi++) {
        const int r0 = wy * 32 + mi * 16 + g;
        const int r1 = r0 + 8;
        const float z0 = gm / Zf[r0];
        const float z1 = gm / Zf[r1];
        #pragma unroll
        for (int ni = 0; ni < 8; ni++) {
            const int c = wx * 64 + ni * 8 + 2 * t;
            size_t i00 = ((size_t)b * CC + c)     * NN + m0 + r0;
            size_t i10 = ((size_t)b * CC + c + 1) * NN + m0 + r0;
            size_t i01 = i00 + 8;   // row r1 = r0+8 along m
            size_t i11 = i10 + 8;
            out[i00] = x[i00] + z0 * acc[mi][ni][0];
            out[i10] = x[i10] + z0 * acc[mi][ni][1];
            out[i01] = x[i01] + z1 * acc[mi][ni][2];
            out[i11] = x[i11] + z1 * acc[mi][ni][3];
        }
    }
}

// ---------------------------------------------------------------------------
extern "C" void kernel_launch(void* const* d_in, const int* in_sizes, int n_in,
                              void* d_out, int out_size)
{
    const float* x     = (const float*)d_in[0];
    const float* Wq    = (const float*)d_in[1];
    const float* bq    = (const float*)d_in[2];
    const float* Wk    = (const float*)d_in[3];
    const float* bk    = (const float*)d_in[4];
    const float* Wv    = (const float*)d_in[5];
    const float* bv    = (const float*)d_in[6];
    const float* gamma = (const float*)d_in[7];
    float* out = (float*)d_out;

    cudaFuncSetAttribute(qkv_mma_kernel,
                         cudaFuncAttributeMaxDynamicSharedMemorySize, QKV_SMEM);
    cudaFuncSetAttribute(attn_fused_kernel,
                         cudaFuncAttributeMaxDynamicSharedMemorySize, FUSED_SMEM);

    qkv_mma_kernel<<<dim3(NN / 128, RR / 64, BB), 256, QKV_SMEM>>>(
        x, Wq, bq, Wk, bk, Wv, bv);
    attn_fused_kernel<<<dim3(NN / 128, 1, BB), 512, FUSED_SMEM>>>(x, gamma, out);
}